// round 7
// baseline (speedup 1.0000x reference)
#include <cuda_runtime.h>

#define NB 64
#define NT 256
#define TBL 32
#define BT (NB*NT)
#define BNS 0.9999950000374997f

__constant__ int c_s2j[25] = {0,1,2,3,20, 4,5,6,7,21,22, 8,9,10,11,23,24, 12,13,14,15, 16,17,18,19};
__constant__ int c_gstart[5] = {0,5,11,17,21};
__constant__ int c_gn[5]     = {5,6,6,4,4};

__device__ float g_adj[5][6][6];
__device__ float g_H [BT*25*64];
__device__ float g_Z [BT*25*128];
__device__ float g_Y1[BT*25*64];
__device__ float g_Y2[BT*25*128];
__device__ float g_Y3[BT*25*64];
__device__ float g_feat[5*64*64];
__device__ float g_loss[5*64];
__device__ float g_sw1[5*64*64],  g_sb1[5*64];
__device__ float g_sw2[5*128*64], g_sb2[5*128];
__device__ float g_sw3[5*64*128], g_sb3[5*64];
__device__ float g_rw2[5*128*64], g_rw3[5*64*128];
__device__ float g_cst2[5*128],   g_cst3[5*64];
__device__ float g_tw1[5*3*64*64], g_tw2[5*3*128*128], g_tw3[5*3*64*64];

__global__ __launch_bounds__(256) void k_prep(
    const float* __restrict__ sw1, const float* __restrict__ sb1,
    const float* __restrict__ tw1,
    const float* __restrict__ rw2, const float* __restrict__ rb2,
    const float* __restrict__ rg2, const float* __restrict__ rbb2,
    const float* __restrict__ sw2, const float* __restrict__ sb2,
    const float* __restrict__ tw2, const float* __restrict__ tb2,
    const float* __restrict__ rw3, const float* __restrict__ rb3,
    const float* __restrict__ rg3, const float* __restrict__ rbb3,
    const float* __restrict__ sw3, const float* __restrict__ sb3,
    const float* __restrict__ tw3, const float* __restrict__ tb3)
{
    int gt  = blockIdx.x*blockDim.x + threadIdx.x;
    int NTH = gridDim.x*blockDim.x;
    for (int i=gt;i<5*64*64;i+=NTH){
        int g=i/4096, r=i%4096, o=r/64, c=r%64;
        const float* w = sw1 + g*192*64;
        g_sw1[i] = w[o*64+c] + w[(64+o)*64+c] + w[(128+o)*64+c];
    }
    for (int i=gt;i<5*128*64;i+=NTH){
        int g=i/8192, r=i%8192, o=r/64, c=r%64;
        const float* w = sw2 + g*384*64;
        g_sw2[i] = w[o*64+c] + w[(128+o)*64+c] + w[(256+o)*64+c];
    }
    for (int i=gt;i<5*64*128;i+=NTH){
        int g=i/8192, r=i%8192, o=r/128, c=r%128;
        const float* w = sw3 + g*192*128;
        g_sw3[i] = w[o*128+c] + w[(64+o)*128+c] + w[(128+o)*128+c];
    }
    for (int i=gt;i<5*128*64;i+=NTH){
        int g=i/8192, o=(i%8192)/64;
        g_rw2[i] = rw2[i] * rg2[g*128+o] * BNS;
    }
    for (int i=gt;i<5*64*128;i+=NTH){
        int g=i/8192, o=(i%8192)/128;
        g_rw3[i] = rw3[i] * rg3[g*64+o] * BNS;
    }
    for (int i=gt;i<5*3*64*64;i+=NTH){
        int c=i%64, o=(i/64)%64, kt=(i/4096)%3, g=i/12288;
        g_tw1[i] = tw1[((g*64+o)*64+c)*3+kt];
        g_tw3[i] = tw3[((g*64+o)*64+c)*3+kt];
    }
    for (int i=gt;i<5*3*128*128;i+=NTH){
        int c=i%128, o=(i/128)%128, kt=(i/16384)%3, g=i/49152;
        g_tw2[i] = tw2[((g*128+o)*128+c)*3+kt];
    }
    for (int i=gt;i<5*64;i+=NTH){
        int g=i/64, o=i%64;
        const float* s1 = sb1 + g*192;
        g_sb1[i]  = s1[o] + s1[64+o] + s1[128+o];
        const float* s3 = sb3 + g*192;
        g_sb3[i]  = s3[o] + s3[64+o] + s3[128+o];
        g_cst3[i] = tb3[i] + rb3[i]*rg3[i]*BNS + rbb3[i];
    }
    for (int i=gt;i<5*128;i+=NTH){
        int g=i/128, o=i%128;
        const float* s = sb2 + g*384;
        g_sb2[i]  = s[o] + s[128+o] + s[256+o];
        g_cst2[i] = tb2[i] + rb2[i]*rg2[i]*BNS + rbb2[i];
    }
    if (gt==0){
        double fa[25][25];
        for (int i=0;i<25;i++) for (int j=0;j<25;j++) fa[i][j]=0.0;
        const int E[24][2]={{3,2},{2,20},{20,1},{1,0},{20,4},{4,5},{5,6},{6,22},
                            {6,7},{7,21},{20,8},{8,9},{9,10},{10,24},{10,11},{11,23},
                            {0,12},{12,13},{13,14},{14,15},{0,16},{16,17},{17,18},{18,19}};
        for (int k=0;k<24;k++){
            int i=E[k][0]-1, j=E[k][1]-1;
            fa[i][j]=1.0; fa[j][i]=1.0;
        }
        for (int i=0;i<25;i++) fa[i][i]+=1.0;
        for (int i=0;i<25;i++){
            double d=0; for (int j=0;j<25;j++) d+=fa[i][j];
            if (d==0.0) d=1.0;
            for (int j=0;j<25;j++) fa[i][j]/=d;
        }
        for (int g=0;g<5;g++){
            int n=c_gn[g];
            int js[6]; for (int u=0;u<n;u++) js[u]=c_s2j[c_gstart[g]+u];
            double sa[6][6];
            for (int u=0;u<n;u++) for (int v=0;v<n;v++) sa[u][v]=fa[js[u]][js[v]];
            for (int u=0;u<n;u++) sa[u][u]+=1.0;
            double dg[6];
            for (int u=0;u<n;u++){ double d=0; for (int v=0;v<n;v++) d+=sa[u][v]; dg[u]=d; }
            for (int node=1;node<n;node++)
                if (dg[node]==1.0){ sa[0][node]=1.0; sa[node][0]=1.0; }
            for (int u=0;u<6;u++) for (int v=0;v<6;v++){
                float val=0.f;
                if (u<n && v<n){
                    double d=0; for (int w=0;w<n;w++) d+=sa[u][w];
                    if (d==0.0) d=1.0;
                    val=(float)(sa[u][v]/d);
                }
                g_adj[g][u][v]=val;
            }
        }
    }
}

__global__ __launch_bounds__(256) void k_embed(const float* __restrict__ x,
                                               const float* __restrict__ ew,
                                               const float* __restrict__ eb)
{
    int idx = blockIdx.x*256 + threadIdx.x;
    int c   = idx & 63;
    int row = idx >> 6;
    int s   = row % 25;
    int bt  = row / 25;
    int j   = c_s2j[s];
    const float* xp = x + (bt*25 + j)*3;
    g_H[idx] = eb[c] + xp[0]*ew[c*3+0] + xp[1]*ew[c*3+1] + xp[2]*ew[c*3+2];
}

__device__ __forceinline__ float dot4s(float acc, float4 a, float4 w){
    return fmaf(a.w,w.w, fmaf(a.z,w.z, fmaf(a.y,w.y, fmaf(a.x,w.x, acc))));
}

// GCN: 192-row tile, 6x8 per-thread tile, full W staged once, sync-free mainloop
template<int CIN,int COUT>
__global__ __launch_bounds__((COUT/8)*32) void k_gcn(const float* __restrict__ Y,
                                                     float* __restrict__ Z,
                                                     const float* __restrict__ W,
                                                     const float* __restrict__ Bv)
{
    constexpr int CT = COUT/8;
    constexpr int TH = CT*32;
    constexpr int C4 = CIN/4;
    constexpr int PR = C4+1;
    extern __shared__ float sm[];
    float4* sA4 = (float4*)sm;                  // [192][PR]
    float4* sW4 = ((float4*)sm) + 192*PR;       // [C4][COUT+1]
    __shared__ float sAdj[6][6];

    const int g   = blockIdx.y;
    const int n   = c_gn[g];
    const int gs0 = c_gstart[g];
    const int bt0 = blockIdx.x * TBL;
    const int tid = threadIdx.x;
    if (tid < 36) sAdj[tid/6][tid%6] = g_adj[g][tid/6][tid%6];
    __syncthreads();

    for (int p=tid; p<192*C4; p+=TH){
        int c4 = p % C4, r = p / C4, u = r % 6, t = r / 6;
        float4 acc = make_float4(0.f,0.f,0.f,0.f);
        if (u < n){
            const float4* yp = (const float4*)(Y + ((size_t)(bt0+t)*25 + gs0)*CIN) + c4;
            #pragma unroll
            for (int v=0; v<6; ++v)
                if (v < n){
                    float av = sAdj[u][v];
                    float4 yv = yp[(size_t)v*C4];
                    acc.x += av*yv.x; acc.y += av*yv.y; acc.z += av*yv.z; acc.w += av*yv.w;
                }
        }
        sA4[r*PR + c4] = acc;
    }
    const float* Wg = W + g*COUT*CIN;
    for (int p=tid; p<COUT*C4; p+=TH){
        int o = p / C4, kk4 = p % C4;
        sW4[kk4*(COUT+1) + o] = *(const float4*)(Wg + o*CIN + kk4*4);
    }
    __syncthreads();

    const int ty = tid / CT, tx = tid % CT;
    float acc[6][8];
    #pragma unroll
    for (int j=0;j<8;++j){
        float b = Bv[g*COUT + tx + CT*j];
        #pragma unroll
        for (int i=0;i<6;++i) acc[i][j]=b;
    }

    #pragma unroll 2
    for (int kk4=0;kk4<C4;++kk4){
        const float4* wb = sW4 + kk4*(COUT+1) + tx;
        float4 w[8];
        #pragma unroll
        for (int j=0;j<8;++j) w[j]=wb[CT*j];
        #pragma unroll
        for (int i=0;i<6;++i){
            float4 a = sA4[(ty+32*i)*PR + kk4];
            #pragma unroll
            for (int j=0;j<8;++j) acc[i][j] = dot4s(acc[i][j], a, w[j]);
        }
    }
    #pragma unroll
    for (int i=0;i<6;++i){
        int r = ty+32*i, t = r/6, u = r%6;
        if (u < n){
            float* zp = Z + ((size_t)(bt0+t)*25 + gs0+u)*COUT + tx;
            #pragma unroll
            for (int j=0;j<8;++j) zp[CT*j] = acc[i][j];
        }
    }
}

// tconv: 192-row tile + halo; CIN==64 -> full 3-tap W staged once (sync-free mainloop);
// CIN==128 -> per-kt staging. Residual GEMM staged after.
template<int CIN,int COUT,int CRES,int MODE>
__global__ __launch_bounds__((COUT/8)*32) void k_tconv(const float* __restrict__ Zin,
                                                       const float* __restrict__ Yres,
                                                       float* __restrict__ Yout,
                                                       const float* __restrict__ TWt,
                                                       const float* __restrict__ RW,
                                                       const float* __restrict__ CST,
                                                       const float* __restrict__ GS,
                                                       const float* __restrict__ BB)
{
    constexpr int CT = COUT/8;
    constexpr int TH = CT*32;
    constexpr int C4 = CIN/4;
    constexpr int R4 = CRES/4;
    constexpr int PRZ = C4+1;
    constexpr int PRR = R4+1;
    constexpr bool FULLW = (CIN==64);
    constexpr int SZ4 = (TBL+2)*6*PRZ;
    constexpr int SR4 = (MODE==1 ? 192*PRR : 0);
    constexpr int SBUF4 = (SZ4 > SR4 ? SZ4 : SR4);
    extern __shared__ float sm[];
    float4* sB4 = (float4*)sm;
    float4* sW4 = ((float4*)sm) + SBUF4;     // FULLW: [3*C4][COUT+1]; else [C4][COUT+1]

    const int g   = blockIdx.y;
    const int n   = c_gn[g];
    const int gs0 = c_gstart[g];
    const int bt0 = blockIdx.x * TBL;
    const int t0  = bt0 & (NT-1);
    const int tid = threadIdx.x, ty = tid/CT, tx = tid%CT;

    for (int p=tid; p<(TBL+2)*6*C4; p+=TH){
        int c4 = p % C4, r = p / C4, u = r % 6, hb = r / 6;
        int t = t0 + hb - 1;
        float4 v = make_float4(0.f,0.f,0.f,0.f);
        if (u < n && t >= 0 && t < NT)
            v = ((const float4*)(Zin + ((size_t)(bt0+hb-1)*25 + gs0+u)*CIN))[c4];
        sB4[r*PRZ + c4] = v;
    }

    float acc[6][8];
    #pragma unroll
    for (int i=0;i<6;++i)
        #pragma unroll
        for (int j=0;j<8;++j) acc[i][j]=0.f;

    const float* TWg = TWt + g*3*COUT*CIN;

    if (FULLW){
        for (int p=tid; p<3*COUT*C4; p+=TH){
            int kt = p / (COUT*C4), r = p % (COUT*C4);
            int o = r / C4, kk4 = r % C4;
            sW4[(kt*C4+kk4)*(COUT+1) + o] = *(const float4*)(TWg + kt*COUT*CIN + o*CIN + kk4*4);
        }
        __syncthreads();
        #pragma unroll
        for (int kt=0;kt<3;++kt){
            #pragma unroll 2
            for (int kk4=0;kk4<C4;++kk4){
                const float4* wb = sW4 + (kt*C4+kk4)*(COUT+1) + tx;
                float4 w[8];
                #pragma unroll
                for (int j=0;j<8;++j) w[j]=wb[CT*j];
                #pragma unroll
                for (int i=0;i<6;++i){
                    float4 a = sB4[(ty+32*i + 6*kt)*PRZ + kk4];
                    #pragma unroll
                    for (int j=0;j<8;++j) acc[i][j] = dot4s(acc[i][j], a, w[j]);
                }
            }
        }
    } else {
        for (int kt=0;kt<3;++kt){
            __syncthreads();
            for (int p=tid; p<COUT*C4; p+=TH){
                int o = p / C4, kk4 = p % C4;
                sW4[kk4*(COUT+1) + o] = *(const float4*)(TWg + kt*COUT*CIN + o*CIN + kk4*4);
            }
            __syncthreads();
            #pragma unroll 2
            for (int kk4=0;kk4<C4;++kk4){
                const float4* wb = sW4 + kk4*(COUT+1) + tx;
                float4 w[8];
                #pragma unroll
                for (int j=0;j<8;++j) w[j]=wb[CT*j];
                #pragma unroll
                for (int i=0;i<6;++i){
                    float4 a = sB4[(ty+32*i + 6*kt)*PRZ + kk4];
                    #pragma unroll
                    for (int j=0;j<8;++j) acc[i][j] = dot4s(acc[i][j], a, w[j]);
                }
            }
        }
    }

    if (MODE==1){
        __syncthreads();
        for (int p=tid; p<192*R4; p+=TH){
            int c4 = p % R4, r = p / R4, u = r % 6, t = r / 6;
            float4 v = make_float4(0.f,0.f,0.f,0.f);
            if (u < n)
                v = ((const float4*)(Yres + ((size_t)(bt0+t)*25 + gs0+u)*CRES))[c4];
            sB4[r*PRR + c4] = v;
        }
        const float* RWg = RW + g*COUT*CRES;
        for (int p=tid; p<COUT*R4; p+=TH){
            int o = p / R4, kk4 = p % R4;
            sW4[kk4*(COUT+1) + o] = *(const float4*)(RWg + o*CRES + kk4*4);
        }
        __syncthreads();
        #pragma unroll 2
        for (int kk4=0;kk4<R4;++kk4){
            const float4* wb = sW4 + kk4*(COUT+1) + tx;
            float4 w[8];
            #pragma unroll
            for (int j=0;j<8;++j) w[j]=wb[CT*j];
            #pragma unroll
            for (int i=0;i<6;++i){
                float4 a = sB4[(ty+32*i)*PRR + kk4];
                #pragma unroll
                for (int j=0;j<8;++j) acc[i][j] = dot4s(acc[i][j], a, w[j]);
            }
        }
    }

    float cst[8], gsv[8], bbv[8];
    #pragma unroll
    for (int j=0;j<8;++j){
        cst[j] = CST[g*COUT + tx + CT*j];
        gsv[j] = GS [g*COUT + tx + CT*j]*BNS;
        bbv[j] = BB [g*COUT + tx + CT*j];
    }
    #pragma unroll
    for (int i=0;i<6;++i){
        int r = ty+32*i, t = r/6, u = r%6;
        if (u < n){
            size_t base = ((size_t)(bt0+t)*25 + gs0+u)*COUT + tx;
            #pragma unroll
            for (int j=0;j<8;++j){
                float pre = acc[i][j] + cst[j];
                if (MODE==0) pre += Yres[base + CT*j];
                Yout[base + CT*j] = fmaxf(pre*gsv[j] + bbv[j], 0.f);
            }
        }
    }
}

__global__ __launch_bounds__(256) void k_feat()
{
    int g = blockIdx.x, b = blockIdx.y;
    int tid = threadIdx.x;
    int o = tid & 63, part = tid >> 6;
    int n = c_gn[g], gs0 = c_gstart[g];
    float s = 0.f;
    int total = NT*n;
    for (int q=part; q<total; q+=4){
        int t = q / n, u = q % n;
        s += g_Y3[((size_t)(b*NT+t)*25 + gs0+u)*64 + o];
    }
    __shared__ float red[256];
    red[tid]=s; __syncthreads();
    if (part==0)
        g_feat[(g*64+b)*64 + o] = (red[o]+red[64+o]+red[128+o]+red[192+o]) / (float)(NT*n);
}

__global__ __launch_bounds__(128) void k_vq(const float* __restrict__ cb,
                                            float* __restrict__ out)
{
    int g = blockIdx.x, b = blockIdx.y;
    int k = threadIdx.x;
    const float* f   = g_feat + (g*64+b)*64;
    const float* ck  = cb + (g*128 + k)*64;
    float dot=0.f, scb=0.f;
    for (int o=0;o<64;++o){ dot += f[o]*ck[o]; scb += ck[o]*ck[o]; }
    float d = scb - 2.f*dot;

    __shared__ float ds[128];
    __shared__ int   sidx;
    ds[k]=d; __syncthreads();
    if (k==0){
        float best = ds[0]; int bi = 0;
        for (int kk=1;kk<128;++kk) if (ds[kk] < best){ best = ds[kk]; bi = kk; }
        sidx = bi;
    }
    __syncthreads();
    int idx = sidx;
    const float* cq = cb + (g*128 + idx)*64;
    __shared__ float dsq[64];
    if (k < 64){
        float q = cq[k];
        out[(g*64+b)*64 + k] = q;
        float dd = q - f[k];
        dsq[k] = dd*dd;
    }
    __syncthreads();
    if (k==0){
        float s=0.f;
        for (int o=0;o<64;++o) s += dsq[o];
        g_loss[g*64+b] = 1.25f * s / 4096.f;
        out[5*64*64 + 1 + g*64 + b] = (float)idx;
    }
}

__global__ void k_lred(float* out){
    __shared__ float s[320];
    int t = threadIdx.x;
    if (t < 320) s[t] = g_loss[t];
    __syncthreads();
    if (t==0){
        float a=0.f;
        for (int i=0;i<320;i++) a += s[i];
        out[5*64*64] = a;
    }
}

extern "C" void kernel_launch(void* const* d_in, const int* in_sizes, int n_in,
                              void* d_out, int out_size)
{
    const float* x        = (const float*)d_in[0];
    const float* embed_w  = (const float*)d_in[1];
    const float* embed_b  = (const float*)d_in[2];
    const float* sgcn_w1  = (const float*)d_in[3];
    const float* sgcn_b1  = (const float*)d_in[4];
    const float* tconv_w1 = (const float*)d_in[5];
    const float* tconv_b1 = (const float*)d_in[6];
    const float* bn_g1    = (const float*)d_in[7];
    const float* bn_b1    = (const float*)d_in[8];
    const float* res_w2   = (const float*)d_in[9];
    const float* res_b2   = (const float*)d_in[10];
    const float* resbn_g2 = (const float*)d_in[11];
    const float* resbn_b2 = (const float*)d_in[12];
    const float* sgcn_w2  = (const float*)d_in[13];
    const float* sgcn_b2  = (const float*)d_in[14];
    const float* tconv_w2 = (const float*)d_in[15];
    const float* tconv_b2 = (const float*)d_in[16];
    const float* bn_g2    = (const float*)d_in[17];
    const float* bn_b2    = (const float*)d_in[18];
    const float* res_w3   = (const float*)d_in[19];
    const float* res_b3   = (const float*)d_in[20];
    const float* resbn_g3 = (const float*)d_in[21];
    const float* resbn_b3 = (const float*)d_in[22];
    const float* sgcn_w3  = (const float*)d_in[23];
    const float* sgcn_b3  = (const float*)d_in[24];
    const float* tconv_w3 = (const float*)d_in[25];
    const float* tconv_b3 = (const float*)d_in[26];
    const float* bn_g3    = (const float*)d_in[27];
    const float* bn_b3    = (const float*)d_in[28];
    const float* codebooks= (const float*)d_in[29];
    float* out = (float*)d_out;

    void *vp;
    #define SYM(name, s) cudaGetSymbolAddress(&vp, s); float* name = (float*)vp;
    SYM(pH,  g_H)  SYM(pZ,  g_Z)  SYM(pY1, g_Y1) SYM(pY2, g_Y2) SYM(pY3, g_Y3)
    SYM(pSW1,g_sw1) SYM(pSB1,g_sb1) SYM(pSW2,g_sw2) SYM(pSB2,g_sb2)
    SYM(pSW3,g_sw3) SYM(pSB3,g_sb3) SYM(pRW2,g_rw2) SYM(pRW3,g_rw3)
    SYM(pC2, g_cst2) SYM(pC3, g_cst3)
    SYM(pTW1,g_tw1) SYM(pTW2,g_tw2) SYM(pTW3,g_tw3)
    #undef SYM

    dim3 grid(BT/TBL, 5);   // 512 x 5

    // smem bytes (float4 counts * 16)
    size_t sm_g1 = (192*17 + 16*65 )*16;                       // ~68.9 KB
    size_t sm_g2 = (192*17 + 16*129)*16;                       // ~85.2 KB
    size_t sm_g3 = (192*33 + 32*65 )*16;                       // ~134.7 KB
    size_t sm_t1 = (204*17 + 3*16*65)*16;                      // ~105.4 KB
    size_t sm_t2 = (204*33 + 32*129)*16;                       // ~173.8 KB
    size_t sm_t3 = (192*33 + 3*16*65)*16;                      // ~151.3 KB

    cudaFuncSetAttribute(k_gcn<64,64>,           cudaFuncAttributeMaxDynamicSharedMemorySize, (int)sm_g1);
    cudaFuncSetAttribute(k_gcn<64,128>,          cudaFuncAttributeMaxDynamicSharedMemorySize, (int)sm_g2);
    cudaFuncSetAttribute(k_gcn<128,64>,          cudaFuncAttributeMaxDynamicSharedMemorySize, (int)sm_g3);
    cudaFuncSetAttribute(k_tconv<64,64,64,0>,    cudaFuncAttributeMaxDynamicSharedMemorySize, (int)sm_t1);
    cudaFuncSetAttribute(k_tconv<128,128,64,1>,  cudaFuncAttributeMaxDynamicSharedMemorySize, (int)sm_t2);
    cudaFuncSetAttribute(k_tconv<64,64,128,1>,   cudaFuncAttributeMaxDynamicSharedMemorySize, (int)sm_t3);

    k_prep<<<64,256>>>(sgcn_w1, sgcn_b1, tconv_w1,
                       res_w2, res_b2, resbn_g2, resbn_b2, sgcn_w2, sgcn_b2, tconv_w2, tconv_b2,
                       res_w3, res_b3, resbn_g3, resbn_b3, sgcn_w3, sgcn_b3, tconv_w3, tconv_b3);

    k_embed<<<BT*25*64/256, 256>>>(x, embed_w, embed_b);

    k_gcn<64,64><<<grid,256,sm_g1>>>(pH, pZ, pSW1, pSB1);
    k_tconv<64,64,64,0><<<grid,256,sm_t1>>>(pZ, pH, pY1, pTW1, nullptr, tconv_b1, bn_g1, bn_b1);
    k_gcn<64,128><<<grid,512,sm_g2>>>(pY1, pZ, pSW2, pSB2);
    k_tconv<128,128,64,1><<<grid,512,sm_t2>>>(pZ, pY1, pY2, pTW2, pRW2, pC2, bn_g2, bn_b2);
    k_gcn<128,64><<<grid,256,sm_g3>>>(pY2, pZ, pSW3, pSB3);
    k_tconv<64,64,128,1><<<grid,256,sm_t3>>>(pZ, pY2, pY3, pTW3, pRW3, pC3, bn_g3, bn_b3);

    k_feat<<<dim3(5,64),256>>>();
    k_vq<<<dim3(5,64),128>>>(codebooks, out);
    k_lred<<<1,512>>>(out);
}

// round 8
// speedup vs baseline: 1.1421x; 1.1421x over previous
#include <cuda_runtime.h>

#define NB 64
#define NT 256
#define BT (NB*NT)
#define BNS 0.9999950000374997f

__constant__ int c_s2j[25] = {0,1,2,3,20, 4,5,6,7,21,22, 8,9,10,11,23,24, 12,13,14,15, 16,17,18,19};
__constant__ int c_gstart[5] = {0,5,11,17,21};
__constant__ int c_gn[5]     = {5,6,6,4,4};

__device__ float g_adj[5][6][6];
__device__ float g_H [BT*25*64];
__device__ float g_Z [BT*25*128];
__device__ float g_Y1[BT*25*64];
__device__ float g_Y2[BT*25*128];
__device__ float g_Y3[BT*25*64];
__device__ float g_feat[5*64*64];
__device__ float g_loss[5*64];
__device__ float g_sb1[5*64], g_sb2[5*128], g_sb3[5*64];
__device__ float g_cst2[5*128], g_cst3[5*64];
// interleaved weights: float4 {W[oa][k],W[ob][k],W[oa][k+1],W[ob][k+1]}
__device__ float4 g_sw1i[5120];    // gcn1: 5 * 32kk2 * 32q
__device__ float4 g_sw2i[10240];   // gcn2: 5 * 32 * 64
__device__ float4 g_sw3i[10240];   // gcn3: 5 * 64 * 32
__device__ float4 g_rw2i[10240];   // res2: 5 * 32 * 64
__device__ float4 g_rw3i[10240];   // res3: 5 * 64 * 32
__device__ float4 g_tw1i[15360];   // tconv1: 5*3 * 32 * 32
__device__ float4 g_tw2i[61440];   // tconv2: 5*3 * 64 * 64
__device__ float4 g_tw3i[15360];   // tconv3

__device__ __forceinline__ unsigned long long bc2(float x){
    unsigned long long r; unsigned u = __float_as_uint(x);
    asm("mov.b64 %0, {%1, %1};" : "=l"(r) : "r"(u));
    return r;
}
__device__ __forceinline__ unsigned long long pk2(float a, float b){
    unsigned long long r;
    asm("mov.b64 %0, {%1, %2};" : "=l"(r) : "r"(__float_as_uint(a)), "r"(__float_as_uint(b)));
    return r;
}
__device__ __forceinline__ void ffma2(unsigned long long& c, unsigned long long a, unsigned long long b){
    asm("fma.rn.f32x2 %0, %1, %2, %0;" : "+l"(c) : "l"(a), "l"(b));
}
__device__ __forceinline__ void unpk(unsigned long long v, float& lo, float& hi){
    unsigned a,b; asm("mov.b64 {%0, %1}, %2;" : "=r"(a), "=r"(b) : "l"(v));
    lo = __uint_as_float(a); hi = __uint_as_float(b);
}

__global__ __launch_bounds__(256) void k_prep(
    const float* __restrict__ sw1, const float* __restrict__ sb1,
    const float* __restrict__ tw1,
    const float* __restrict__ rw2, const float* __restrict__ rb2,
    const float* __restrict__ rg2, const float* __restrict__ rbb2,
    const float* __restrict__ sw2, const float* __restrict__ sb2,
    const float* __restrict__ tw2, const float* __restrict__ tb2,
    const float* __restrict__ rw3, const float* __restrict__ rb3,
    const float* __restrict__ rg3, const float* __restrict__ rbb3,
    const float* __restrict__ sw3, const float* __restrict__ sb3,
    const float* __restrict__ tw3, const float* __restrict__ tb3)
{
    int gt  = blockIdx.x*blockDim.x + threadIdx.x;
    int NTH = gridDim.x*blockDim.x;

    // gcn1: COUT=64 CIN=64 CT=8
    for (int e=gt;e<5120;e+=NTH){
        int g=e/1024, r=e%1024, kk2=r/32, q=r%32, jp=q/8, tx=q%8;
        int oa=tx+16*jp, ob=oa+8, k0=2*kk2;
        const float* w = sw1 + g*192*64;
        #define S1(o,c) (w[(o)*64+(c)] + w[(64+(o))*64+(c)] + w[(128+(o))*64+(c)])
        g_sw1i[e] = make_float4(S1(oa,k0), S1(ob,k0), S1(oa,k0+1), S1(ob,k0+1));
        #undef S1
    }
    // gcn2: COUT=128 CIN=64 CT=16
    for (int e=gt;e<10240;e+=NTH){
        int g=e/2048, r=e%2048, kk2=r/64, q=r%64, jp=q/16, tx=q%16;
        int oa=tx+32*jp, ob=oa+16, k0=2*kk2;
        const float* w = sw2 + g*384*64;
        #define S2(o,c) (w[(o)*64+(c)] + w[(128+(o))*64+(c)] + w[(256+(o))*64+(c)])
        g_sw2i[e] = make_float4(S2(oa,k0), S2(ob,k0), S2(oa,k0+1), S2(ob,k0+1));
        #undef S2
    }
    // gcn3: COUT=64 CIN=128 CT=8
    for (int e=gt;e<10240;e+=NTH){
        int g=e/2048, r=e%2048, kk2=r/32, q=r%32, jp=q/8, tx=q%8;
        int oa=tx+16*jp, ob=oa+8, k0=2*kk2;
        const float* w = sw3 + g*192*128;
        #define S3(o,c) (w[(o)*128+(c)] + w[(64+(o))*128+(c)] + w[(128+(o))*128+(c)])
        g_sw3i[e] = make_float4(S3(oa,k0), S3(ob,k0), S3(oa,k0+1), S3(ob,k0+1));
        #undef S3
    }
    // res2: COUT=128 CIN=64 CT=16
    for (int e=gt;e<10240;e+=NTH){
        int g=e/2048, r=e%2048, kk2=r/64, q=r%64, jp=q/16, tx=q%16;
        int oa=tx+32*jp, ob=oa+16, k0=2*kk2;
        const float* w = rw2 + g*8192;
        float sa_=rg2[g*128+oa]*BNS, sb_=rg2[g*128+ob]*BNS;
        g_rw2i[e] = make_float4(w[oa*64+k0]*sa_, w[ob*64+k0]*sb_, w[oa*64+k0+1]*sa_, w[ob*64+k0+1]*sb_);
    }
    // res3: COUT=64 CIN=128 CT=8
    for (int e=gt;e<10240;e+=NTH){
        int g=e/2048, r=e%2048, kk2=r/32, q=r%32, jp=q/8, tx=q%8;
        int oa=tx+16*jp, ob=oa+8, k0=2*kk2;
        const float* w = rw3 + g*8192;
        float sa_=rg3[g*64+oa]*BNS, sb_=rg3[g*64+ob]*BNS;
        g_rw3i[e] = make_float4(w[oa*128+k0]*sa_, w[ob*128+k0]*sb_, w[oa*128+k0+1]*sa_, w[ob*128+k0+1]*sb_);
    }
    // tconv1/3: COUT=64 CIN=64 KT=3 CT=8
    for (int e=gt;e<15360;e+=NTH){
        int g=e/3072, r=e%3072, kt=r/1024, r2=r%1024, kk2=r2/32, q=r2%32, jp=q/8, tx=q%8;
        int oa=tx+16*jp, ob=oa+8, k0=2*kk2;
        #define T1(w,o,c) (w[(((g)*64+(o))*64+(c))*3+kt])
        g_tw1i[e] = make_float4(T1(tw1,oa,k0), T1(tw1,ob,k0), T1(tw1,oa,k0+1), T1(tw1,ob,k0+1));
        g_tw3i[e] = make_float4(T1(tw3,oa,k0), T1(tw3,ob,k0), T1(tw3,oa,k0+1), T1(tw3,ob,k0+1));
        #undef T1
    }
    // tconv2: COUT=128 CIN=128 KT=3 CT=16
    for (int e=gt;e<61440;e+=NTH){
        int g=e/12288, r=e%12288, kt=r/4096, r2=r%4096, kk2=r2/64, q=r2%64, jp=q/16, tx=q%16;
        int oa=tx+32*jp, ob=oa+16, k0=2*kk2;
        #define T2(o,c) (tw2[(((g)*128+(o))*128+(c))*3+kt])
        g_tw2i[e] = make_float4(T2(oa,k0), T2(ob,k0), T2(oa,k0+1), T2(ob,k0+1));
        #undef T2
    }
    for (int i=gt;i<5*64;i+=NTH){
        int g=i/64, o=i%64;
        const float* s1 = sb1 + g*192;
        g_sb1[i]  = s1[o] + s1[64+o] + s1[128+o];
        const float* s3 = sb3 + g*192;
        g_sb3[i]  = s3[o] + s3[64+o] + s3[128+o];
        g_cst3[i] = tb3[i] + rb3[i]*rg3[i]*BNS + rbb3[i];
    }
    for (int i=gt;i<5*128;i+=NTH){
        int g=i/128, o=i%128;
        const float* s = sb2 + g*384;
        g_sb2[i]  = s[o] + s[128+o] + s[256+o];
        g_cst2[i] = tb2[i] + rb2[i]*rg2[i]*BNS + rbb2[i];
    }
    if (gt==0){
        double fa[25][25];
        for (int i=0;i<25;i++) for (int j=0;j<25;j++) fa[i][j]=0.0;
        const int E[24][2]={{3,2},{2,20},{20,1},{1,0},{20,4},{4,5},{5,6},{6,22},
                            {6,7},{7,21},{20,8},{8,9},{9,10},{10,24},{10,11},{11,23},
                            {0,12},{12,13},{13,14},{14,15},{0,16},{16,17},{17,18},{18,19}};
        for (int k=0;k<24;k++){
            int i=E[k][0]-1, j=E[k][1]-1;
            fa[i][j]=1.0; fa[j][i]=1.0;
        }
        for (int i=0;i<25;i++) fa[i][i]+=1.0;
        for (int i=0;i<25;i++){
            double d=0; for (int j=0;j<25;j++) d+=fa[i][j];
            if (d==0.0) d=1.0;
            for (int j=0;j<25;j++) fa[i][j]/=d;
        }
        for (int g=0;g<5;g++){
            int n=c_gn[g];
            int js[6]; for (int u=0;u<n;u++) js[u]=c_s2j[c_gstart[g]+u];
            double sa[6][6];
            for (int u=0;u<n;u++) for (int v=0;v<n;v++) sa[u][v]=fa[js[u]][js[v]];
            for (int u=0;u<n;u++) sa[u][u]+=1.0;
            double dg[6];
            for (int u=0;u<n;u++){ double d=0; for (int v=0;v<n;v++) d+=sa[u][v]; dg[u]=d; }
            for (int node=1;node<n;node++)
                if (dg[node]==1.0){ sa[0][node]=1.0; sa[node][0]=1.0; }
            for (int u=0;u<6;u++) for (int v=0;v<6;v++){
                float val=0.f;
                if (u<n && v<n){
                    double d=0; for (int w=0;w<n;w++) d+=sa[u][w];
                    if (d==0.0) d=1.0;
                    val=(float)(sa[u][v]/d);
                }
                g_adj[g][u][v]=val;
            }
        }
    }
}

__global__ __launch_bounds__(256) void k_embed(const float* __restrict__ x,
                                               const float* __restrict__ ew,
                                               const float* __restrict__ eb)
{
    int idx = blockIdx.x*256 + threadIdx.x;
    int c   = idx & 63;
    int row = idx >> 6;
    int s   = row % 25;
    int bt  = row / 25;
    int j   = c_s2j[s];
    const float* xp = x + (bt*25 + j)*3;
    g_H[idx] = eb[c] + xp[0]*ew[c*3+0] + xp[1]*ew[c*3+1] + xp[2]*ew[c*3+2];
}

// one kk4 step (4 k): 6 rows x 8 cols via f32x2. aPtr -> float4 at (row ty, kk4), stride between rows.
template<int CT>
__device__ __forceinline__ void gemm_kk4(unsigned long long (&acc)[6][4],
                                         const float4* aPtr, int aStride,
                                         const ulonglong2* wPtr)
{
    float4 a[6];
    #pragma unroll
    for (int i=0;i<6;++i) a[i] = aPtr[aStride*i];
    #pragma unroll
    for (int h=0;h<2;++h){
        ulonglong2 w0 = wPtr[h*4*CT + 0*CT];
        ulonglong2 w1 = wPtr[h*4*CT + 1*CT];
        ulonglong2 w2 = wPtr[h*4*CT + 2*CT];
        ulonglong2 w3 = wPtr[h*4*CT + 3*CT];
        #pragma unroll
        for (int i=0;i<6;++i){
            unsigned long long alo = bc2(h ? a[i].z : a[i].x);
            unsigned long long ahi = bc2(h ? a[i].w : a[i].y);
            ffma2(acc[i][0], alo, w0.x);
            ffma2(acc[i][1], alo, w1.x);
            ffma2(acc[i][2], alo, w2.x);
            ffma2(acc[i][3], alo, w3.x);
            ffma2(acc[i][0], ahi, w0.y);
            ffma2(acc[i][1], ahi, w1.y);
            ffma2(acc[i][2], ahi, w2.y);
            ffma2(acc[i][3], ahi, w3.y);
        }
    }
}

template<int CIN,int COUT,int ROWS>
__global__ __launch_bounds__((COUT/8)*(ROWS/6), ((COUT/8)*(ROWS/6))==256?2:1)
void k_gcn(const float* __restrict__ Y, float* __restrict__ Z,
           const float4* __restrict__ Wi, const float* __restrict__ Bv)
{
    constexpr int CT  = COUT/8;
    constexpr int TYS = ROWS/6;
    constexpr int TH  = CT*TYS;
    constexpr int C4  = CIN/4;
    constexpr int C2  = CIN/2;
    constexpr int PR  = C4+1;
    constexpr int TBLG= ROWS/6;
    constexpr bool HALF = (CIN==128);
    constexpr int WENT = (HALF ? 32 : C2)*4*CT;
    extern __shared__ float sm[];
    float4* sA4 = (float4*)sm;                 // [ROWS][PR]
    float4* sW4 = sA4 + ROWS*PR;               // [WENT]
    const ulonglong2* sWl = (const ulonglong2*)sW4;
    __shared__ float sAdj[6][6];

    const int g   = blockIdx.y;
    const int n   = c_gn[g];
    const int gs0 = c_gstart[g];
    const int bt0 = blockIdx.x * TBLG;
    const int tid = threadIdx.x;
    if (tid < 36) sAdj[tid/6][tid%6] = g_adj[g][tid/6][tid%6];
    __syncthreads();

    for (int p=tid; p<ROWS*C4; p+=TH){
        int c4 = p % C4, r = p / C4, u = r % 6, t = r / 6;
        float4 acc = make_float4(0.f,0.f,0.f,0.f);
        if (u < n){
            const float4* yp = (const float4*)(Y + ((size_t)(bt0+t)*25 + gs0)*CIN) + c4;
            #pragma unroll
            for (int v=0; v<6; ++v)
                if (v < n){
                    float av = sAdj[u][v];
                    float4 yv = yp[(size_t)v*C4];
                    acc.x += av*yv.x; acc.y += av*yv.y; acc.z += av*yv.z; acc.w += av*yv.w;
                }
        }
        sA4[r*PR + c4] = acc;
    }

    const int ty = tid / CT, tx = tid % CT;
    unsigned long long acc[6][4];
    #pragma unroll
    for (int jp=0;jp<4;++jp){
        int oa = tx + CT*2*jp;
        unsigned long long b2 = pk2(Bv[g*COUT+oa], Bv[g*COUT+oa+CT]);
        #pragma unroll
        for (int i=0;i<6;++i) acc[i][jp]=b2;
    }
    const float4* Wg = Wi + (size_t)g*(C2*4*CT);

    if (!HALF){
        for (int p=tid; p<WENT; p+=TH) sW4[p] = Wg[p];
        __syncthreads();
        #pragma unroll 4
        for (int kk4=0;kk4<C4;++kk4)
            gemm_kk4<CT>(acc, sA4 + ty*PR + kk4, TYS*PR, sWl + 2*kk4*4*CT + tx);
    } else {
        for (int ph=0; ph<2; ++ph){
            if (ph) __syncthreads();
            for (int p=tid; p<WENT; p+=TH) sW4[p] = Wg[ph*WENT + p];
            __syncthreads();
            #pragma unroll 4
            for (int kk4l=0;kk4l<16;++kk4l)
                gemm_kk4<CT>(acc, sA4 + ty*PR + ph*16 + kk4l, TYS*PR, sWl + 2*kk4l*4*CT + tx);
        }
    }

    #pragma unroll
    for (int i=0;i<6;++i){
        int r = ty+TYS*i, t = r/6, u = r%6;
        if (u < n){
            float* zp = Z + ((size_t)(bt0+t)*25 + gs0+u)*COUT;
            #pragma unroll
            for (int jp=0;jp<4;++jp){
                float lo,hi; unpk(acc[i][jp], lo, hi);
                int oa = tx + CT*2*jp;
                zp[oa] = lo; zp[oa+CT] = hi;
            }
        }
    }
}

template<int CIN,int COUT,int CRES,int MODE>
__global__ __launch_bounds__((COUT/8)*32, ((COUT/8)*32)==256?2:1)
void k_tconv(const float* __restrict__ Zin, const float* __restrict__ Yres,
             float* __restrict__ Yout,
             const float4* __restrict__ TWi, const float4* __restrict__ RWi,
             const float* __restrict__ CST, const float* __restrict__ GS,
             const float* __restrict__ BB)
{
    constexpr int CT  = COUT/8;
    constexpr int TH  = CT*32;
    constexpr int C4  = CIN/4;
    constexpr int C2  = CIN/2;
    constexpr int PRZ = C4+1;
    constexpr int TBL = 32;
    constexpr bool FULLW = (CIN==64);
    constexpr int WKT   = C2*4*CT;                 // entries per kt
    constexpr int WENT  = FULLW ? 3*WKT : WKT;
    constexpr int SBUF4 = (TBL+2)*6*PRZ;
    extern __shared__ float sm[];
    float4* sB4 = (float4*)sm;
    float4* sW4 = sB4 + SBUF4;
    const ulonglong2* sWl = (const ulonglong2*)sW4;

    const int g   = blockIdx.y;
    const int n   = c_gn[g];
    const int gs0 = c_gstart[g];
    const int bt0 = blockIdx.x * TBL;
    const int t0  = bt0 & (NT-1);
    const int tid = threadIdx.x, ty = tid/CT, tx = tid%CT;

    for (int p=tid; p<(TBL+2)*6*C4; p+=TH){
        int c4 = p % C4, r = p / C4, u = r % 6, hb = r / 6;
        int t = t0 + hb - 1;
        float4 v = make_float4(0.f,0.f,0.f,0.f);
        if (u < n && t >= 0 && t < NT)
            v = ((const float4*)(Zin + ((size_t)(bt0+hb-1)*25 + gs0+u)*CIN))[c4];
        sB4[r*PRZ + c4] = v;
    }

    unsigned long long acc[6][4];
    unsigned long long z2 = pk2(0.f, 0.f);
    #pragma unroll
    for (int i=0;i<6;++i)
        #pragma unroll
        for (int jp=0;jp<4;++jp) acc[i][jp]=z2;

    const float4* TWg = TWi + (size_t)g*3*WKT;

    if (FULLW){
        for (int p=tid; p<WENT; p+=TH) sW4[p] = TWg[p];
        __syncthreads();
        #pragma unroll
        for (int kt=0;kt<3;++kt){
            #pragma unroll 4
            for (int kk4=0;kk4<C4;++kk4)
                gemm_kk4<CT>(acc, sB4 + (ty+6*kt)*PRZ + kk4, 32*PRZ,
                             sWl + kt*WKT + 2*kk4*4*CT + tx);
        }
    } else {
        for (int kt=0;kt<3;++kt){
            __syncthreads();
            for (int p=tid; p<WKT; p+=TH) sW4[p] = TWg[kt*WKT + p];
            __syncthreads();
            #pragma unroll 4
            for (int kk4=0;kk4<C4;++kk4)
                gemm_kk4<CT>(acc, sB4 + (ty+6*kt)*PRZ + kk4, 32*PRZ,
                             sWl + 2*kk4*4*CT + tx);
        }
    }

    if (MODE==1){
        // residual GEMM in 64-k passes: res rows 192 x 16 f4 (pitch 17), RW 32 kk2 per pass
        constexpr int RPASS = CRES/64;
        constexpr int R4    = CRES/4;
        constexpr int RWP   = 32*4*CT;     // RW entries per pass
        const float4* RWg = RWi + (size_t)g*2048;
        for (int ph=0; ph<RPASS; ++ph){
            __syncthreads();
            for (int p=tid; p<192*16; p+=TH){
                int c4l = p % 16, r = p / 16, u = r % 6, t = r / 6;
                float4 v = make_float4(0.f,0.f,0.f,0.f);
                if (u < n)
                    v = ((const float4*)(Yres + ((size_t)(bt0+t)*25 + gs0+u)*CRES))[ph*16 + c4l];
                sB4[r*17 + c4l] = v;
            }
            for (int p=tid; p<RWP; p+=TH) sW4[p] = RWg[ph*RWP + p];
            __syncthreads();
            #pragma unroll 4
            for (int kk4l=0;kk4l<16;++kk4l)
                gemm_kk4<CT>(acc, sB4 + ty*17 + kk4l, 32*17, sWl + 2*kk4l*4*CT + tx);
        }
        (void)R4;
    }

    float cst[8], gsv[8], bbv[8];
    #pragma unroll
    for (int jp=0;jp<4;++jp){
        int oa = tx + CT*2*jp;
        cst[2*jp]   = CST[g*COUT+oa];       cst[2*jp+1] = CST[g*COUT+oa+CT];
        gsv[2*jp]   = GS [g*COUT+oa]*BNS;   gsv[2*jp+1] = GS [g*COUT+oa+CT]*BNS;
        bbv[2*jp]   = BB [g*COUT+oa];       bbv[2*jp+1] = BB [g*COUT+oa+CT];
    }
    #pragma unroll
    for (int i=0;i<6;++i){
        int r = ty+32*i, t = r/6, u = r%6;
        if (u < n){
            size_t base = ((size_t)(bt0+t)*25 + gs0+u)*COUT;
            #pragma unroll
            for (int jp=0;jp<4;++jp){
                float lo,hi; unpk(acc[i][jp], lo, hi);
                int oa = tx + CT*2*jp;
                float pa = lo + cst[2*jp];
                float pb = hi + cst[2*jp+1];
                if (MODE==0){ pa += Yres[base+oa]; pb += Yres[base+oa+CT]; }
                Yout[base+oa]    = fmaxf(pa*gsv[2*jp]   + bbv[2*jp],   0.f);
                Yout[base+oa+CT] = fmaxf(pb*gsv[2*jp+1] + bbv[2*jp+1], 0.f);
            }
        }
    }
}

__global__ __launch_bounds__(256) void k_feat()
{
    int g = blockIdx.x, b = blockIdx.y;
    int tid = threadIdx.x;
    int o = tid & 63, part = tid >> 6;
    int n = c_gn[g], gs0 = c_gstart[g];
    float s = 0.f;
    int total = NT*n;
    for (int q=part; q<total; q+=4){
        int t = q / n, u = q % n;
        s += g_Y3[((size_t)(b*NT+t)*25 + gs0+u)*64 + o];
    }
    __shared__ float red[256];
    red[tid]=s; __syncthreads();
    if (part==0)
        g_feat[(g*64+b)*64 + o] = (red[o]+red[64+o]+red[128+o]+red[192+o]) / (float)(NT*n);
}

__global__ __launch_bounds__(128) void k_vq(const float* __restrict__ cb,
                                            float* __restrict__ out)
{
    int g = blockIdx.x, b = blockIdx.y;
    int k = threadIdx.x;
    const float* f   = g_feat + (g*64+b)*64;
    const float* ck  = cb + (g*128 + k)*64;
    float dot=0.f, scb=0.f;
    for (int o=0;o<64;++o){ dot += f[o]*ck[o]; scb += ck[o]*ck[o]; }
    float d = scb - 2.f*dot;

    __shared__ float ds[128];
    __shared__ int   sidx;
    ds[k]=d; __syncthreads();
    if (k==0){
        float best = ds[0]; int bi = 0;
        for (int kk=1;kk<128;++kk) if (ds[kk] < best){ best = ds[kk]; bi = kk; }
        sidx = bi;
    }
    __syncthreads();
    int idx = sidx;
    const float* cq = cb + (g*128 + idx)*64;
    __shared__ float dsq[64];
    if (k < 64){
        float q = cq[k];
        out[(g*64+b)*64 + k] = q;
        float dd = q - f[k];
        dsq[k] = dd*dd;
    }
    __syncthreads();
    if (k==0){
        float s=0.f;
        for (int o=0;o<64;++o) s += dsq[o];
        g_loss[g*64+b] = 1.25f * s / 4096.f;
        out[5*64*64 + 1 + g*64 + b] = (float)idx;
    }
}

__global__ void k_lred(float* out){
    __shared__ float s[320];
    int t = threadIdx.x;
    if (t < 320) s[t] = g_loss[t];
    __syncthreads();
    if (t==0){
        float a=0.f;
        for (int i=0;i<320;i++) a += s[i];
        out[5*64*64] = a;
    }
}

extern "C" void kernel_launch(void* const* d_in, const int* in_sizes, int n_in,
                              void* d_out, int out_size)
{
    const float* x        = (const float*)d_in[0];
    const float* embed_w  = (const float*)d_in[1];
    const float* embed_b  = (const float*)d_in[2];
    const float* sgcn_w1  = (const float*)d_in[3];
    const float* sgcn_b1  = (const float*)d_in[4];
    const float* tconv_w1 = (const float*)d_in[5];
    const float* tconv_b1 = (const float*)d_in[6];
    const float* bn_g1    = (const float*)d_in[7];
    const float* bn_b1    = (const float*)d_in[8];
    const float* res_w2   = (const float*)d_in[9];
    const float* res_b2   = (const float*)d_in[10];
    const float* resbn_g2 = (const float*)d_in[11];
    const float* resbn_b2 = (const float*)d_in[12];
    const float* sgcn_w2  = (const float*)d_in[13];
    const float* sgcn_b2  = (const float*)d_in[14];
    const float* tconv_w2 = (const float*)d_in[15];
    const float* tconv_b2 = (const float*)d_in[16];
    const float* bn_g2    = (const float*)d_in[17];
    const float* bn_b2    = (const float*)d_in[18];
    const float* res_w3   = (const float*)d_in[19];
    const float* res_b3   = (const float*)d_in[20];
    const float* resbn_g3 = (const float*)d_in[21];
    const float* resbn_b3 = (const float*)d_in[22];
    const float* sgcn_w3  = (const float*)d_in[23];
    const float* sgcn_b3  = (const float*)d_in[24];
    const float* tconv_w3 = (const float*)d_in[25];
    const float* tconv_b3 = (const float*)d_in[26];
    const float* bn_g3    = (const float*)d_in[27];
    const float* bn_b3    = (const float*)d_in[28];
    const float* codebooks= (const float*)d_in[29];
    float* out = (float*)d_out;

    void *vp;
    #define SYM(name, s, T) cudaGetSymbolAddress(&vp, s); T* name = (T*)vp;
    SYM(pH,  g_H,  float)  SYM(pZ, g_Z, float)  SYM(pY1, g_Y1, float)
    SYM(pY2, g_Y2, float)  SYM(pY3, g_Y3, float)
    SYM(pSB1,g_sb1,float) SYM(pSB2,g_sb2,float) SYM(pSB3,g_sb3,float)
    SYM(pC2, g_cst2,float) SYM(pC3, g_cst3,float)
    SYM(pSW1,g_sw1i,float4) SYM(pSW2,g_sw2i,float4) SYM(pSW3,g_sw3i,float4)
    SYM(pRW2,g_rw2i,float4) SYM(pRW3,g_rw3i,float4)
    SYM(pTW1,g_tw1i,float4) SYM(pTW2,g_tw2i,float4) SYM(pTW3,g_tw3i,float4)
    #undef SYM

    dim3 grid32(BT/32, 5);
    dim3 grid64(BT/64, 5);

    size_t sm_g1 = (192*17 + 1024)*16;       // 68.6 KB
    size_t sm_g2 = (192*17 + 2048)*16;       // 85.0 KB
    size_t sm_g3 = (384*33 + 1024)*16;       // 219.1 KB
    size_t sm_t1 = (204*17 + 3072)*16;       // 104.6 KB
    size_t sm_t2 = (204*33 + 4096)*16;       // 173.2 KB
    size_t sm_t3 = (204*17 + 3072)*16;       // 104.6 KB

    cudaFuncSetAttribute(k_gcn<64,64,192>,       cudaFuncAttributeMaxDynamicSharedMemorySize, (int)sm_g1);
    cudaFuncSetAttribute(k_gcn<64,128,192>,      cudaFuncAttributeMaxDynamicSharedMemorySize, (int)sm_g2);
    cudaFuncSetAttribute(k_gcn<128,64,384>,      cudaFuncAttributeMaxDynamicSharedMemorySize, (int)sm_g3);
    cudaFuncSetAttribute(k_tconv<64,64,64,0>,    cudaFuncAttributeMaxDynamicSharedMemorySize, (int)sm_t1);
    cudaFuncSetAttribute(k_tconv<128,128,64,1>,  cudaFuncAttributeMaxDynamicSharedMemorySize, (int)sm_t2);
    cudaFuncSetAttribute(k_tconv<64,64,128,1>,   cudaFuncAttributeMaxDynamicSharedMemorySize, (int)sm_t3);

    k_prep<<<64,256>>>(sgcn_w1, sgcn_b1, tconv_w1,
                       res_w2, res_b2, resbn_g2, resbn_b2, sgcn_w2, sgcn_b2, tconv_w2, tconv_b2,
                       res_w3, res_b3, resbn_g3, resbn_b3, sgcn_w3, sgcn_b3, tconv_w3, tconv_b3);

    k_embed<<<BT*25*64/256, 256>>>(x, embed_w, embed_b);

    k_gcn<64,64,192><<<grid32,256,sm_g1>>>(pH, pZ, pSW1, pSB1);
    k_tconv<64,64,64,0><<<grid32,256,sm_t1>>>(pZ, pH, pY1, pTW1, pRW2, tconv_b1, bn_g1, bn_b1);
    k_gcn<64,128,192><<<grid32,512,sm_g2>>>(pY1, pZ, pSW2, pSB2);
    k_tconv<128,128,64,1><<<grid32,512,sm_t2>>>(pZ, pY1, pY2, pTW2, pRW2, pC2, bn_g2, bn_b2);
    k_gcn<128,64,384><<<grid64,512,sm_g3>>>(pY2, pZ, pSW3, pSB3);
    k_tconv<64,64,128,1><<<grid32,256,sm_t3>>>(pZ, pY2, pY3, pTW3, pRW3, pC3, bn_g3, bn_b3);

    k_feat<<<dim3(5,64),256>>>();
    k_vq<<<dim3(5,64),128>>>(codebooks, out);
    k_lred<<<1,512>>>(out);
}

// round 9
// speedup vs baseline: 1.4462x; 1.2663x over previous
#include <cuda_runtime.h>

#define NB 64
#define NT 256
#define BT (NB*NT)
#define BNS 0.9999950000374997f

__constant__ int c_s2j[25] = {0,1,2,3,20, 4,5,6,7,21,22, 8,9,10,11,23,24, 12,13,14,15, 16,17,18,19};
__constant__ int c_gstart[5] = {0,5,11,17,21};
__constant__ int c_gn[5]     = {5,6,6,4,4};

__device__ float g_adj[5][6][6];
__device__ float g_H [BT*25*64];
__device__ float g_Z [BT*25*64];
__device__ float g_Y1[BT*25*64];
__device__ float g_Y2[BT*25*128];
__device__ float g_Y3[BT*25*64];
__device__ float g_feat[5*64*64];
__device__ float g_loss[5*64];
__device__ float g_sb3[5*64];
__device__ float g_cst1[5*64],  g_bb0_1[5*64],  g_bb2_1[5*64];
__device__ float g_cst2[5*128], g_bb0_2[5*128], g_bb2_2[5*128];
__device__ float g_cst3[5*64];
__device__ float g_zero[640];
// interleaved weights: float4 {W[oa][k],W[ob][k],W[oa][k+1],W[ob][k+1]}
__device__ float4 g_sw3i[10240];   // gcn3: 5 * 64kk2 * 32q
__device__ float4 g_rw2i[10240];   // res2: 5 * 32 * 64
__device__ float4 g_rw3i[10240];   // res3: 5 * 64 * 32
__device__ float4 g_tw1i[15360];   // fused tconv1: 5*3 * 32 * 32 (composite Wt1@Sw1)
__device__ float4 g_tw2i[30720];   // fused tconv2: 5*3 * 32 * 64 (composite Wt2@Sw2)
__device__ float4 g_tw3i[15360];   // tconv3 plain

__device__ __forceinline__ unsigned long long bc2(float x){
    unsigned long long r; unsigned u = __float_as_uint(x);
    asm("mov.b64 %0, {%1, %1};" : "=l"(r) : "r"(u));
    return r;
}
__device__ __forceinline__ unsigned long long pk2(float a, float b){
    unsigned long long r;
    asm("mov.b64 %0, {%1, %2};" : "=l"(r) : "r"(__float_as_uint(a)), "r"(__float_as_uint(b)));
    return r;
}
__device__ __forceinline__ void ffma2(unsigned long long& c, unsigned long long a, unsigned long long b){
    asm("fma.rn.f32x2 %0, %1, %2, %0;" : "+l"(c) : "l"(a), "l"(b));
}
__device__ __forceinline__ void unpk(unsigned long long v, float& lo, float& hi){
    unsigned a,b; asm("mov.b64 {%0, %1}, %2;" : "=r"(a), "=r"(b) : "l"(v));
    lo = __uint_as_float(a); hi = __uint_as_float(b);
}

__global__ __launch_bounds__(256) void k_prep(
    const float* __restrict__ sw1, const float* __restrict__ sb1,
    const float* __restrict__ tw1, const float* __restrict__ tb1,
    const float* __restrict__ rw2, const float* __restrict__ rb2,
    const float* __restrict__ rg2, const float* __restrict__ rbb2,
    const float* __restrict__ sw2, const float* __restrict__ sb2,
    const float* __restrict__ tw2, const float* __restrict__ tb2,
    const float* __restrict__ rw3, const float* __restrict__ rb3,
    const float* __restrict__ rg3, const float* __restrict__ rbb3,
    const float* __restrict__ sw3, const float* __restrict__ sb3,
    const float* __restrict__ tw3, const float* __restrict__ tb3)
{
    int gt  = blockIdx.x*blockDim.x + threadIdx.x;
    int NTH = gridDim.x*blockDim.x;

    // fused tconv1 composite: W1c[kt] = Wt1[kt] @ Sw1fold  (64x64 per kt)
    for (int e=gt;e<15360;e+=NTH){
        int g=e/3072, r=e%3072, kt=r/1024, r2=r%1024, kk2=r2/32, q=r2%32, jp=q/8, tx=q%8;
        int oa=tx+16*jp, ob=oa+8, k0=2*kk2;
        float v0=0.f,v1=0.f,v2=0.f,v3=0.f;
        for (int c=0;c<64;c++){
            float s0 = sw1[(g*192+c)*64+k0]   + sw1[(g*192+64+c)*64+k0]   + sw1[(g*192+128+c)*64+k0];
            float s1 = sw1[(g*192+c)*64+k0+1] + sw1[(g*192+64+c)*64+k0+1] + sw1[(g*192+128+c)*64+k0+1];
            float wa = tw1[((g*64+oa)*64+c)*3+kt];
            float wb = tw1[((g*64+ob)*64+c)*3+kt];
            v0=fmaf(wa,s0,v0); v1=fmaf(wb,s0,v1); v2=fmaf(wa,s1,v2); v3=fmaf(wb,s1,v3);
        }
        g_tw1i[e]=make_float4(v0,v1,v2,v3);
    }
    // tconv3 plain interleave (CT=8)
    for (int e=gt;e<15360;e+=NTH){
        int g=e/3072, r=e%3072, kt=r/1024, r2=r%1024, kk2=r2/32, q=r2%32, jp=q/8, tx=q%8;
        int oa=tx+16*jp, ob=oa+8, k0=2*kk2;
        g_tw3i[e]=make_float4(tw3[((g*64+oa)*64+k0)*3+kt],   tw3[((g*64+ob)*64+k0)*3+kt],
                              tw3[((g*64+oa)*64+k0+1)*3+kt], tw3[((g*64+ob)*64+k0+1)*3+kt]);
    }
    // fused tconv2 composite: W2c[kt] = Wt2[kt] @ Sw2fold  (128x64 per kt), CT=16
    for (int e=gt;e<30720;e+=NTH){
        int g=e/6144, r=e%6144, kt=r/2048, r2=r%2048, kk2=r2/64, q=r2%64, jp=q/16, tx=q%16;
        int oa=tx+32*jp, ob=oa+16, k0=2*kk2;
        float v0=0.f,v1=0.f,v2=0.f,v3=0.f;
        for (int c=0;c<128;c++){
            float s0 = sw2[(g*384+c)*64+k0]   + sw2[(g*384+128+c)*64+k0]   + sw2[(g*384+256+c)*64+k0];
            float s1 = sw2[(g*384+c)*64+k0+1] + sw2[(g*384+128+c)*64+k0+1] + sw2[(g*384+256+c)*64+k0+1];
            float wa = tw2[((g*128+oa)*128+c)*3+kt];
            float wb = tw2[((g*128+ob)*128+c)*3+kt];
            v0=fmaf(wa,s0,v0); v1=fmaf(wb,s0,v1); v2=fmaf(wa,s1,v2); v3=fmaf(wb,s1,v3);
        }
        g_tw2i[e]=make_float4(v0,v1,v2,v3);
    }
    // gcn3 interleave (CIN=128, CT=8)
    for (int e=gt;e<10240;e+=NTH){
        int g=e/2048, r=e%2048, kk2=r/32, q=r%32, jp=q/8, tx=q%8;
        int oa=tx+16*jp, ob=oa+8, k0=2*kk2;
        const float* w = sw3 + g*192*128;
        #define S3(o,c) (w[(o)*128+(c)] + w[(64+(o))*128+(c)] + w[(128+(o))*128+(c)])
        g_sw3i[e] = make_float4(S3(oa,k0), S3(ob,k0), S3(oa,k0+1), S3(ob,k0+1));
        #undef S3
    }
    // res2 interleave (COUT=128, CRES=64, CT=16)
    for (int e=gt;e<10240;e+=NTH){
        int g=e/2048, r=e%2048, kk2=r/64, q=r%64, jp=q/16, tx=q%16;
        int oa=tx+32*jp, ob=oa+16, k0=2*kk2;
        const float* w = rw2 + g*8192;
        float sa_=rg2[g*128+oa]*BNS, sb_=rg2[g*128+ob]*BNS;
        g_rw2i[e] = make_float4(w[oa*64+k0]*sa_, w[ob*64+k0]*sb_, w[oa*64+k0+1]*sa_, w[ob*64+k0+1]*sb_);
    }
    // res3 interleave (COUT=64, CRES=128, CT=8)
    for (int e=gt;e<10240;e+=NTH){
        int g=e/2048, r=e%2048, kk2=r/32, q=r%32, jp=q/8, tx=q%8;
        int oa=tx+16*jp, ob=oa+8, k0=2*kk2;
        const float* w = rw3 + g*8192;
        float sa_=rg3[g*64+oa]*BNS, sb_=rg3[g*64+ob]*BNS;
        g_rw3i[e] = make_float4(w[oa*128+k0]*sa_, w[ob*128+k0]*sb_, w[oa*128+k0+1]*sa_, w[ob*128+k0+1]*sb_);
    }
    // L1 constants: bb1[kt] = Wt1[kt]@sb1fold ; cst1 = tb1 + sum_kt bb1
    for (int i=gt;i<5*64;i+=NTH){
        int g=i/64, o=i%64;
        float b0=0.f,b1=0.f,b2=0.f;
        for (int c=0;c<64;c++){
            float sb = sb1[g*192+c]+sb1[g*192+64+c]+sb1[g*192+128+c];
            b0=fmaf(tw1[((g*64+o)*64+c)*3+0],sb,b0);
            b1=fmaf(tw1[((g*64+o)*64+c)*3+1],sb,b1);
            b2=fmaf(tw1[((g*64+o)*64+c)*3+2],sb,b2);
        }
        g_cst1[i]=tb1[i]+b0+b1+b2;
        g_bb0_1[i]=b0; g_bb2_1[i]=b2;
        const float* s3=sb3+g*192;
        g_sb3[i]=s3[o]+s3[64+o]+s3[128+o];
        g_cst3[i]=tb3[i]+rb3[i]*rg3[i]*BNS+rbb3[i];
    }
    // L2 constants
    for (int i=gt;i<5*128;i+=NTH){
        int g=i/128, o=i%128;
        float b0=0.f,b1=0.f,b2=0.f;
        for (int c=0;c<128;c++){
            float sb = sb2[g*384+c]+sb2[g*384+128+c]+sb2[g*384+256+c];
            b0=fmaf(tw2[((g*128+o)*128+c)*3+0],sb,b0);
            b1=fmaf(tw2[((g*128+o)*128+c)*3+1],sb,b1);
            b2=fmaf(tw2[((g*128+o)*128+c)*3+2],sb,b2);
        }
        g_cst2[i]=tb2[i]+rb2[i]*rg2[i]*BNS+rbb2[i]+b0+b1+b2;
        g_bb0_2[i]=b0; g_bb2_2[i]=b2;
    }
    for (int i=gt;i<640;i+=NTH) g_zero[i]=0.f;
    if (gt==0){
        double fa[25][25];
        for (int i=0;i<25;i++) for (int j=0;j<25;j++) fa[i][j]=0.0;
        const int E[24][2]={{3,2},{2,20},{20,1},{1,0},{20,4},{4,5},{5,6},{6,22},
                            {6,7},{7,21},{20,8},{8,9},{9,10},{10,24},{10,11},{11,23},
                            {0,12},{12,13},{13,14},{14,15},{0,16},{16,17},{17,18},{18,19}};
        for (int k=0;k<24;k++){
            int i=E[k][0]-1, j=E[k][1]-1;
            fa[i][j]=1.0; fa[j][i]=1.0;
        }
        for (int i=0;i<25;i++) fa[i][i]+=1.0;
        for (int i=0;i<25;i++){
            double d=0; for (int j=0;j<25;j++) d+=fa[i][j];
            if (d==0.0) d=1.0;
            for (int j=0;j<25;j++) fa[i][j]/=d;
        }
        for (int g=0;g<5;g++){
            int n=c_gn[g];
            int js[6]; for (int u=0;u<n;u++) js[u]=c_s2j[c_gstart[g]+u];
            double sa[6][6];
            for (int u=0;u<n;u++) for (int v=0;v<n;v++) sa[u][v]=fa[js[u]][js[v]];
            for (int u=0;u<n;u++) sa[u][u]+=1.0;
            double dg[6];
            for (int u=0;u<n;u++){ double d=0; for (int v=0;v<n;v++) d+=sa[u][v]; dg[u]=d; }
            for (int node=1;node<n;node++)
                if (dg[node]==1.0){ sa[0][node]=1.0; sa[node][0]=1.0; }
            for (int u=0;u<6;u++) for (int v=0;v<6;v++){
                float val=0.f;
                if (u<n && v<n){
                    double d=0; for (int w=0;w<n;w++) d+=sa[u][w];
                    if (d==0.0) d=1.0;
                    val=(float)(sa[u][v]/d);
                }
                g_adj[g][u][v]=val;
            }
        }
    }
}

__global__ __launch_bounds__(256) void k_embed(const float* __restrict__ x,
                                               const float* __restrict__ ew,
                                               const float* __restrict__ eb)
{
    int idx = blockIdx.x*256 + threadIdx.x;
    int c   = idx & 63;
    int row = idx >> 6;
    int s   = row % 25;
    int bt  = row / 25;
    int j   = c_s2j[s];
    const float* xp = x + (bt*25 + j)*3;
    g_H[idx] = eb[c] + xp[0]*ew[c*3+0] + xp[1]*ew[c*3+1] + xp[2]*ew[c*3+2];
}

// one kk4 step (4 k): 6 rows x 8 cols via f32x2
template<int CT>
__device__ __forceinline__ void gemm_kk4(unsigned long long (&acc)[6][4],
                                         const float4* aPtr, int aStride,
                                         const ulonglong2* wPtr)
{
    float4 a[6];
    #pragma unroll
    for (int i=0;i<6;++i) a[i] = aPtr[aStride*i];
    #pragma unroll
    for (int h=0;h<2;++h){
        ulonglong2 w0 = wPtr[h*4*CT + 0*CT];
        ulonglong2 w1 = wPtr[h*4*CT + 1*CT];
        ulonglong2 w2 = wPtr[h*4*CT + 2*CT];
        ulonglong2 w3 = wPtr[h*4*CT + 3*CT];
        #pragma unroll
        for (int i=0;i<6;++i){
            unsigned long long alo = bc2(h ? a[i].z : a[i].x);
            unsigned long long ahi = bc2(h ? a[i].w : a[i].y);
            ffma2(acc[i][0], alo, w0.x);
            ffma2(acc[i][1], alo, w1.x);
            ffma2(acc[i][2], alo, w2.x);
            ffma2(acc[i][3], alo, w3.x);
            ffma2(acc[i][0], ahi, w0.y);
            ffma2(acc[i][1], ahi, w1.y);
            ffma2(acc[i][2], ahi, w2.y);
            ffma2(acc[i][3], ahi, w3.y);
        }
    }
}

template<int CIN,int COUT,int ROWS>
__global__ __launch_bounds__((COUT/8)*(ROWS/6), ((COUT/8)*(ROWS/6))==256?2:1)
void k_gcn(const float* __restrict__ Y, float* __restrict__ Z,
           const float4* __restrict__ Wi, const float* __restrict__ Bv)
{
    constexpr int CT  = COUT/8;
    constexpr int TYS = ROWS/6;
    constexpr int TH  = CT*TYS;
    constexpr int C4  = CIN/4;
    constexpr int C2  = CIN/2;
    constexpr int PR  = C4+1;
    constexpr int TBLG= ROWS/6;
    constexpr bool HALF = (CIN==128);
    constexpr int WENT = (HALF ? 32 : C2)*4*CT;
    extern __shared__ float sm[];
    float4* sA4 = (float4*)sm;
    float4* sW4 = sA4 + ROWS*PR;
    const ulonglong2* sWl = (const ulonglong2*)sW4;
    __shared__ float sAdj[6][6];

    const int g   = blockIdx.y;
    const int n   = c_gn[g];
    const int gs0 = c_gstart[g];
    const int bt0 = blockIdx.x * TBLG;
    const int tid = threadIdx.x;
    if (tid < 36) sAdj[tid/6][tid%6] = g_adj[g][tid/6][tid%6];
    __syncthreads();

    for (int p=tid; p<ROWS*C4; p+=TH){
        int c4 = p % C4, r = p / C4, u = r % 6, t = r / 6;
        float4 acc = make_float4(0.f,0.f,0.f,0.f);
        if (u < n){
            const float4* yp = (const float4*)(Y + ((size_t)(bt0+t)*25 + gs0)*CIN) + c4;
            #pragma unroll
            for (int v=0; v<6; ++v)
                if (v < n){
                    float av = sAdj[u][v];
                    float4 yv = yp[(size_t)v*C4];
                    acc.x += av*yv.x; acc.y += av*yv.y; acc.z += av*yv.z; acc.w += av*yv.w;
                }
        }
        sA4[r*PR + c4] = acc;
    }

    const int ty = tid / CT, tx = tid % CT;
    unsigned long long acc[6][4];
    #pragma unroll
    for (int jp=0;jp<4;++jp){
        int oa = tx + CT*2*jp;
        unsigned long long b2 = pk2(Bv[g*COUT+oa], Bv[g*COUT+oa+CT]);
        #pragma unroll
        for (int i=0;i<6;++i) acc[i][jp]=b2;
    }
    const float4* Wg = Wi + (size_t)g*(C2*4*CT);

    if (!HALF){
        for (int p=tid; p<WENT; p+=TH) sW4[p] = Wg[p];
        __syncthreads();
        #pragma unroll 4
        for (int kk4=0;kk4<C4;++kk4)
            gemm_kk4<CT>(acc, sA4 + ty*PR + kk4, TYS*PR, sWl + 2*kk4*4*CT + tx);
    } else {
        for (int ph=0; ph<2; ++ph){
            if (ph) __syncthreads();
            for (int p=tid; p<WENT; p+=TH) sW4[p] = Wg[ph*WENT + p];
            __syncthreads();
            #pragma unroll 4
            for (int kk4l=0;kk4l<16;++kk4l)
                gemm_kk4<CT>(acc, sA4 + ty*PR + ph*16 + kk4l, TYS*PR, sWl + 2*kk4l*4*CT + tx);
        }
    }

    #pragma unroll
    for (int i=0;i<6;++i){
        int r = ty+TYS*i, t = r/6, u = r%6;
        if (u < n){
            float* zp = Z + ((size_t)(bt0+t)*25 + gs0+u)*COUT;
            #pragma unroll
            for (int jp=0;jp<4;++jp){
                float lo,hi; unpk(acc[i][jp], lo, hi);
                int oa = tx + CT*2*jp;
                zp[oa] = lo; zp[oa+CT] = hi;
            }
        }
    }
}

// tconv (optionally fused with graph conv on staging): CIN=64 always here.
template<int CIN,int COUT,int CRES,int MODE,int GCONV>
__global__ __launch_bounds__((COUT/8)*32, ((COUT/8)*32)==256?2:1)
void k_tconv(const float* __restrict__ Zin, const float* __restrict__ Yres,
             float* __restrict__ Yout,
             const float4* __restrict__ TWi, const float4* __restrict__ RWi,
             const float* __restrict__ CST, const float* __restrict__ BB0,
             const float* __restrict__ BB2,
             const float* __restrict__ GS, const float* __restrict__ BB)
{
    constexpr int CT  = COUT/8;
    constexpr int TH  = CT*32;
    constexpr int C4  = CIN/4;
    constexpr int C2  = CIN/2;
    constexpr int PRZ = C4+1;
    constexpr int TBL = 32;
    constexpr int WKT   = C2*4*CT;
    constexpr int WENT  = 3*WKT;
    constexpr int SBUF4 = (TBL+2)*6*PRZ;
    extern __shared__ float sm[];
    float4* sB4 = (float4*)sm;
    float4* sW4 = sB4 + SBUF4;
    const ulonglong2* sWl = (const ulonglong2*)sW4;
    __shared__ float sAdj[6][6];

    const int g   = blockIdx.y;
    const int n   = c_gn[g];
    const int gs0 = c_gstart[g];
    const int bt0 = blockIdx.x * TBL;
    const int t0  = bt0 & (NT-1);
    const int tid = threadIdx.x, ty = tid/CT, tx = tid%CT;

    if (GCONV){
        if (tid < 36) sAdj[tid/6][tid%6] = g_adj[g][tid/6][tid%6];
        __syncthreads();
    }

    for (int p=tid; p<(TBL+2)*6*C4; p+=TH){
        int c4 = p % C4, r = p / C4, u = r % 6, hb = r / 6;
        int t = t0 + hb - 1;
        float4 v = make_float4(0.f,0.f,0.f,0.f);
        if (t >= 0 && t < NT){
            if (GCONV){
                const float4* yp = (const float4*)(Zin + ((size_t)(bt0+hb-1)*25 + gs0)*CIN) + c4;
                #pragma unroll
                for (int vv=0; vv<6; ++vv)
                    if (vv < n){
                        float av = sAdj[u][vv];
                        float4 yv = yp[(size_t)vv*C4];
                        v.x += av*yv.x; v.y += av*yv.y; v.z += av*yv.z; v.w += av*yv.w;
                    }
            } else if (u < n){
                v = ((const float4*)(Zin + ((size_t)(bt0+hb-1)*25 + gs0+u)*CIN))[c4];
            }
        }
        sB4[r*PRZ + c4] = v;
    }

    unsigned long long acc[6][4];
    unsigned long long z2 = pk2(0.f, 0.f);
    #pragma unroll
    for (int i=0;i<6;++i)
        #pragma unroll
        for (int jp=0;jp<4;++jp) acc[i][jp]=z2;

    const float4* TWg = TWi + (size_t)g*WENT;
    for (int p=tid; p<WENT; p+=TH) sW4[p] = TWg[p];
    __syncthreads();
    #pragma unroll
    for (int kt=0;kt<3;++kt){
        #pragma unroll 4
        for (int kk4=0;kk4<C4;++kk4)
            gemm_kk4<CT>(acc, sB4 + (ty+6*kt)*PRZ + kk4, 32*PRZ,
                         sWl + kt*WKT + 2*kk4*4*CT + tx);
    }

    if (MODE==1){
        constexpr int RPASS = CRES/64;
        constexpr int RWP   = 32*4*CT;
        const float4* RWg = RWi + (size_t)g*2048;
        for (int ph=0; ph<RPASS; ++ph){
            __syncthreads();
            for (int p=tid; p<192*16; p+=TH){
                int c4l = p % 16, r = p / 16, u = r % 6, t = r / 6;
                float4 v = make_float4(0.f,0.f,0.f,0.f);
                if (u < n)
                    v = ((const float4*)(Yres + ((size_t)(bt0+t)*25 + gs0+u)*CRES))[ph*16 + c4l];
                sB4[r*17 + c4l] = v;
            }
            for (int p=tid; p<RWP; p+=TH) sW4[p] = RWg[ph*RWP + p];
            __syncthreads();
            #pragma unroll 4
            for (int kk4l=0;kk4l<16;++kk4l)
                gemm_kk4<CT>(acc, sB4 + ty*17 + kk4l, 32*17, sWl + 2*kk4l*4*CT + tx);
        }
    }

    float cst[8], gsv[8], bbv[8];
    #pragma unroll
    for (int jp=0;jp<4;++jp){
        int oa = tx + CT*2*jp;
        cst[2*jp]   = CST[g*COUT+oa];       cst[2*jp+1] = CST[g*COUT+oa+CT];
        gsv[2*jp]   = GS [g*COUT+oa]*BNS;   gsv[2*jp+1] = GS [g*COUT+oa+CT]*BNS;
        bbv[2*jp]   = BB [g*COUT+oa];       bbv[2*jp+1] = BB [g*COUT+oa+CT];
    }
    #pragma unroll
    for (int i=0;i<6;++i){
        int r = ty+32*i, t = r/6, u = r%6;
        if (u < n){
            size_t base = ((size_t)(bt0+t)*25 + gs0+u)*COUT;
            int tg = t0 + t;
            bool e0 = (tg==0), e2 = (tg==NT-1);
            #pragma unroll
            for (int jp=0;jp<4;++jp){
                float lo,hi; unpk(acc[i][jp], lo, hi);
                int oa = tx + CT*2*jp;
                float pa = lo + cst[2*jp];
                float pb = hi + cst[2*jp+1];
                if (e0){ pa -= BB0[g*COUT+oa]; pb -= BB0[g*COUT+oa+CT]; }
                if (e2){ pa -= BB2[g*COUT+oa]; pb -= BB2[g*COUT+oa+CT]; }
                if (MODE==0){ pa += Yres[base+oa]; pb += Yres[base+oa+CT]; }
                Yout[base+oa]    = fmaxf(pa*gsv[2*jp]   + bbv[2*jp],   0.f);
                Yout[base+oa+CT] = fmaxf(pb*gsv[2*jp+1] + bbv[2*jp+1], 0.f);
            }
        }
    }
}

__global__ __launch_bounds__(256) void k_feat()
{
    int g = blockIdx.x, b = blockIdx.y;
    int tid = threadIdx.x;
    int o = tid & 63, part = tid >> 6;
    int n = c_gn[g], gs0 = c_gstart[g];
    float s = 0.f;
    int total = NT*n;
    for (int q=part; q<total; q+=4){
        int t = q / n, u = q % n;
        s += g_Y3[((size_t)(b*NT+t)*25 + gs0+u)*64 + o];
    }
    __shared__ float red[256];
    red[tid]=s; __syncthreads();
    if (part==0)
        g_feat[(g*64+b)*64 + o] = (red[o]+red[64+o]+red[128+o]+red[192+o]) / (float)(NT*n);
}

__global__ __launch_bounds__(128) void k_vq(const float* __restrict__ cb,
                                            float* __restrict__ out)
{
    int g = blockIdx.x, b = blockIdx.y;
    int k = threadIdx.x;
    const float* f   = g_feat + (g*64+b)*64;
    const float* ck  = cb + (g*128 + k)*64;
    float dot=0.f, scb=0.f;
    for (int o=0;o<64;++o){ dot += f[o]*ck[o]; scb += ck[o]*ck[o]; }
    float d = scb - 2.f*dot;

    __shared__ float ds[128];
    __shared__ int   sidx;
    ds[k]=d; __syncthreads();
    if (k==0){
        float best = ds[0]; int bi = 0;
        for (int kk=1;kk<128;++kk) if (ds[kk] < best){ best = ds[kk]; bi = kk; }
        sidx = bi;
    }
    __syncthreads();
    int idx = sidx;
    const float* cq = cb + (g*128 + idx)*64;
    __shared__ float dsq[64];
    if (k < 64){
        float q = cq[k];
        out[(g*64+b)*64 + k] = q;
        float dd = q - f[k];
        dsq[k] = dd*dd;
    }
    __syncthreads();
    if (k==0){
        float s=0.f;
        for (int o=0;o<64;++o) s += dsq[o];
        g_loss[g*64+b] = 1.25f * s / 4096.f;
        out[5*64*64 + 1 + g*64 + b] = (float)idx;
    }
}

__global__ void k_lred(float* out){
    __shared__ float s[320];
    int t = threadIdx.x;
    if (t < 320) s[t] = g_loss[t];
    __syncthreads();
    if (t==0){
        float a=0.f;
        for (int i=0;i<320;i++) a += s[i];
        out[5*64*64] = a;
    }
}

extern "C" void kernel_launch(void* const* d_in, const int* in_sizes, int n_in,
                              void* d_out, int out_size)
{
    const float* x        = (const float*)d_in[0];
    const float* embed_w  = (const float*)d_in[1];
    const float* embed_b  = (const float*)d_in[2];
    const float* sgcn_w1  = (const float*)d_in[3];
    const float* sgcn_b1  = (const float*)d_in[4];
    const float* tconv_w1 = (const float*)d_in[5];
    const float* tconv_b1 = (const float*)d_in[6];
    const float* bn_g1    = (const float*)d_in[7];
    const float* bn_b1    = (const float*)d_in[8];
    const float* res_w2   = (const float*)d_in[9];
    const float* res_b2   = (const float*)d_in[10];
    const float* resbn_g2 = (const float*)d_in[11];
    const float* resbn_b2 = (const float*)d_in[12];
    const float* sgcn_w2  = (const float*)d_in[13];
    const float* sgcn_b2  = (const float*)d_in[14];
    const float* tconv_w2 = (const float*)d_in[15];
    const float* tconv_b2 = (const float*)d_in[16];
    const float* bn_g2    = (const float*)d_in[17];
    const float* bn_b2    = (const float*)d_in[18];
    const float* res_w3   = (const float*)d_in[19];
    const float* res_b3   = (const float*)d_in[20];
    const float* resbn_g3 = (const float*)d_in[21];
    const float* resbn_b3 = (const float*)d_in[22];
    const float* sgcn_w3  = (const float*)d_in[23];
    const float* sgcn_b3  = (const float*)d_in[24];
    const float* tconv_w3 = (const float*)d_in[25];
    const float* tconv_b3 = (const float*)d_in[26];
    const float* bn_g3    = (const float*)d_in[27];
    const float* bn_b3    = (const float*)d_in[28];
    const float* codebooks= (const float*)d_in[29];
    float* out = (float*)d_out;

    void *vp;
    #define SYM(name, s, T) cudaGetSymbolAddress(&vp, s); T* name = (T*)vp;
    SYM(pH,  g_H,  float)  SYM(pZ, g_Z, float)  SYM(pY1, g_Y1, float)
    SYM(pY2, g_Y2, float)  SYM(pY3, g_Y3, float)
    SYM(pSB3,g_sb3,float)
    SYM(pC1, g_cst1,float) SYM(pB01,g_bb0_1,float) SYM(pB21,g_bb2_1,float)
    SYM(pC2, g_cst2,float) SYM(pB02,g_bb0_2,float) SYM(pB22,g_bb2_2,float)
    SYM(pC3, g_cst3,float) SYM(pZERO,g_zero,float)
    SYM(pSW3,g_sw3i,float4)
    SYM(pRW2,g_rw2i,float4) SYM(pRW3,g_rw3i,float4)
    SYM(pTW1,g_tw1i,float4) SYM(pTW2,g_tw2i,float4) SYM(pTW3,g_tw3i,float4)
    #undef SYM

    dim3 grid32(BT/32, 5);
    dim3 grid64(BT/64, 5);

    size_t sm_t1 = (34*6*17 + 3072)*16;     // 104.6 KB
    size_t sm_t2 = (34*6*17 + 6144)*16;     // 153.8 KB
    size_t sm_t3 = sm_t1;
    size_t sm_g3 = (384*33 + 1024)*16;      // 219.1 KB

    cudaFuncSetAttribute(k_tconv<64,64,64,0,1>,   cudaFuncAttributeMaxDynamicSharedMemorySize, (int)sm_t1);
    cudaFuncSetAttribute(k_tconv<64,128,64,1,1>,  cudaFuncAttributeMaxDynamicSharedMemorySize, (int)sm_t2);
    cudaFuncSetAttribute(k_gcn<128,64,384>,       cudaFuncAttributeMaxDynamicSharedMemorySize, (int)sm_g3);
    cudaFuncSetAttribute(k_tconv<64,64,128,1,0>,  cudaFuncAttributeMaxDynamicSharedMemorySize, (int)sm_t3);

    k_prep<<<64,256>>>(sgcn_w1, sgcn_b1, tconv_w1, tconv_b1,
                       res_w2, res_b2, resbn_g2, resbn_b2, sgcn_w2, sgcn_b2, tconv_w2, tconv_b2,
                       res_w3, res_b3, resbn_g3, resbn_b3, sgcn_w3, sgcn_b3, tconv_w3, tconv_b3);

    k_embed<<<BT*25*64/256, 256>>>(x, embed_w, embed_b);

    // Layer 1: fused graph-conv + composite tconv, identity residual (H)
    k_tconv<64,64,64,0,1><<<grid32,256,sm_t1>>>(pH, pH, pY1, pTW1, pRW2,
                                                pC1, pB01, pB21, bn_g1, bn_b1);
    // Layer 2: fused graph-conv + composite tconv (128 out), residual from Y1
    k_tconv<64,128,64,1,1><<<grid32,512,sm_t2>>>(pY1, pY1, pY2, pTW2, pRW2,
                                                 pC2, pB02, pB22, bn_g2, bn_b2);
    // Layer 3: gcn (graph + 128->64 GEMM) then tconv + residual from Y2
    k_gcn<128,64,384><<<grid64,512,sm_g3>>>(pY2, pZ, pSW3, pSB3);
    k_tconv<64,64,128,1,0><<<grid32,256,sm_t3>>>(pZ, pY2, pY3, pTW3, pRW3,
                                                 pC3, pZERO, pZERO, bn_g3, bn_b3);

    k_feat<<<dim3(5,64),256>>>();
    k_vq<<<dim3(5,64),128>>>(codebooks, out);
    k_lred<<<1,512>>>(out);
}

// round 10
// speedup vs baseline: 1.5475x; 1.0700x over previous
#include <cuda_runtime.h>

#define NB 64
#define NT 256
#define BT (NB*NT)
#define BNS 0.9999950000374997f

__constant__ int c_s2j[25] = {0,1,2,3,20, 4,5,6,7,21,22, 8,9,10,11,23,24, 12,13,14,15, 16,17,18,19};
__constant__ int c_gstart[5] = {0,5,11,17,21};
__constant__ int c_gn[5]     = {5,6,6,4,4};

__device__ float g_adj[5][6][6];
__device__ float g_H [BT*25*64];
__device__ float g_Z [BT*25*64];
__device__ float g_Y1[BT*25*64];
__device__ float g_Y2[BT*25*128];
__device__ float g_Y3[BT*25*64];
__device__ float g_loss[5*64];
__device__ float g_sb3[5*64];
__device__ float g_cst1[5*64],  g_bb0_1[5*64],  g_bb2_1[5*64];
__device__ float g_cst2[5*128], g_bb0_2[5*128], g_bb2_2[5*128];
__device__ float g_cst3[5*64];
__device__ float g_zero[640];
__device__ float4 g_sw3i[10240];
__device__ float4 g_rw2i[10240];
__device__ float4 g_rw3i[10240];
__device__ float4 g_tw1i[15360];
__device__ float4 g_tw2i[30720];
__device__ float4 g_tw3i[15360];

__device__ __forceinline__ unsigned long long bc2(float x){
    unsigned long long r; unsigned u = __float_as_uint(x);
    asm("mov.b64 %0, {%1, %1};" : "=l"(r) : "r"(u));
    return r;
}
__device__ __forceinline__ unsigned long long pk2(float a, float b){
    unsigned long long r;
    asm("mov.b64 %0, {%1, %2};" : "=l"(r) : "r"(__float_as_uint(a)), "r"(__float_as_uint(b)));
    return r;
}
__device__ __forceinline__ void ffma2(unsigned long long& c, unsigned long long a, unsigned long long b){
    asm("fma.rn.f32x2 %0, %1, %2, %0;" : "+l"(c) : "l"(a), "l"(b));
}
__device__ __forceinline__ void unpk(unsigned long long v, float& lo, float& hi){
    unsigned a,b; asm("mov.b64 {%0, %1}, %2;" : "=r"(a), "=r"(b) : "l"(v));
    lo = __uint_as_float(a); hi = __uint_as_float(b);
}

__global__ __launch_bounds__(256) void k_prep(
    const float* __restrict__ sw1, const float* __restrict__ sb1,
    const float* __restrict__ tw1, const float* __restrict__ tb1,
    const float* __restrict__ rw2, const float* __restrict__ rb2,
    const float* __restrict__ rg2, const float* __restrict__ rbb2,
    const float* __restrict__ sw2, const float* __restrict__ sb2,
    const float* __restrict__ tw2, const float* __restrict__ tb2,
    const float* __restrict__ rw3, const float* __restrict__ rb3,
    const float* __restrict__ rg3, const float* __restrict__ rbb3,
    const float* __restrict__ sw3, const float* __restrict__ sb3,
    const float* __restrict__ tw3, const float* __restrict__ tb3)
{
    int gt  = blockIdx.x*blockDim.x + threadIdx.x;
    int NTH = gridDim.x*blockDim.x;

    for (int e=gt;e<15360;e+=NTH){
        int g=e/3072, r=e%3072, kt=r/1024, r2=r%1024, kk2=r2/32, q=r2%32, jp=q/8, tx=q%8;
        int oa=tx+16*jp, ob=oa+8, k0=2*kk2;
        float v0=0.f,v1=0.f,v2=0.f,v3=0.f;
        for (int c=0;c<64;c++){
            float s0 = sw1[(g*192+c)*64+k0]   + sw1[(g*192+64+c)*64+k0]   + sw1[(g*192+128+c)*64+k0];
            float s1 = sw1[(g*192+c)*64+k0+1] + sw1[(g*192+64+c)*64+k0+1] + sw1[(g*192+128+c)*64+k0+1];
            float wa = tw1[((g*64+oa)*64+c)*3+kt];
            float wb = tw1[((g*64+ob)*64+c)*3+kt];
            v0=fmaf(wa,s0,v0); v1=fmaf(wb,s0,v1); v2=fmaf(wa,s1,v2); v3=fmaf(wb,s1,v3);
        }
        g_tw1i[e]=make_float4(v0,v1,v2,v3);
    }
    for (int e=gt;e<15360;e+=NTH){
        int g=e/3072, r=e%3072, kt=r/1024, r2=r%1024, kk2=r2/32, q=r2%32, jp=q/8, tx=q%8;
        int oa=tx+16*jp, ob=oa+8, k0=2*kk2;
        g_tw3i[e]=make_float4(tw3[((g*64+oa)*64+k0)*3+kt],   tw3[((g*64+ob)*64+k0)*3+kt],
                              tw3[((g*64+oa)*64+k0+1)*3+kt], tw3[((g*64+ob)*64+k0+1)*3+kt]);
    }
    for (int e=gt;e<30720;e+=NTH){
        int g=e/6144, r=e%6144, kt=r/2048, r2=r%2048, kk2=r2/64, q=r2%64, jp=q/16, tx=q%16;
        int oa=tx+32*jp, ob=oa+16, k0=2*kk2;
        float v0=0.f,v1=0.f,v2=0.f,v3=0.f;
        for (int c=0;c<128;c++){
            float s0 = sw2[(g*384+c)*64+k0]   + sw2[(g*384+128+c)*64+k0]   + sw2[(g*384+256+c)*64+k0];
            float s1 = sw2[(g*384+c)*64+k0+1] + sw2[(g*384+128+c)*64+k0+1] + sw2[(g*384+256+c)*64+k0+1];
            float wa = tw2[((g*128+oa)*128+c)*3+kt];
            float wb = tw2[((g*128+ob)*128+c)*3+kt];
            v0=fmaf(wa,s0,v0); v1=fmaf(wb,s0,v1); v2=fmaf(wa,s1,v2); v3=fmaf(wb,s1,v3);
        }
        g_tw2i[e]=make_float4(v0,v1,v2,v3);
    }
    for (int e=gt;e<10240;e+=NTH){
        int g=e/2048, r=e%2048, kk2=r/32, q=r%32, jp=q/8, tx=q%8;
        int oa=tx+16*jp, ob=oa+8, k0=2*kk2;
        const float* w = sw3 + g*192*128;
        #define S3(o,c) (w[(o)*128+(c)] + w[(64+(o))*128+(c)] + w[(128+(o))*128+(c)])
        g_sw3i[e] = make_float4(S3(oa,k0), S3(ob,k0), S3(oa,k0+1), S3(ob,k0+1));
        #undef S3
    }
    for (int e=gt;e<10240;e+=NTH){
        int g=e/2048, r=e%2048, kk2=r/64, q=r%64, jp=q/16, tx=q%16;
        int oa=tx+32*jp, ob=oa+16, k0=2*kk2;
        const float* w = rw2 + g*8192;
        float sa_=rg2[g*128+oa]*BNS, sb_=rg2[g*128+ob]*BNS;
        g_rw2i[e] = make_float4(w[oa*64+k0]*sa_, w[ob*64+k0]*sb_, w[oa*64+k0+1]*sa_, w[ob*64+k0+1]*sb_);
    }
    for (int e=gt;e<10240;e+=NTH){
        int g=e/2048, r=e%2048, kk2=r/32, q=r%32, jp=q/8, tx=q%8;
        int oa=tx+16*jp, ob=oa+8, k0=2*kk2;
        const float* w = rw3 + g*8192;
        float sa_=rg3[g*64+oa]*BNS, sb_=rg3[g*64+ob]*BNS;
        g_rw3i[e] = make_float4(w[oa*128+k0]*sa_, w[ob*128+k0]*sb_, w[oa*128+k0+1]*sa_, w[ob*128+k0+1]*sb_);
    }
    for (int i=gt;i<5*64;i+=NTH){
        int g=i/64, o=i%64;
        float b0=0.f,b1=0.f,b2=0.f;
        for (int c=0;c<64;c++){
            float sb = sb1[g*192+c]+sb1[g*192+64+c]+sb1[g*192+128+c];
            b0=fmaf(tw1[((g*64+o)*64+c)*3+0],sb,b0);
            b1=fmaf(tw1[((g*64+o)*64+c)*3+1],sb,b1);
            b2=fmaf(tw1[((g*64+o)*64+c)*3+2],sb,b2);
        }
        g_cst1[i]=tb1[i]+b0+b1+b2;
        g_bb0_1[i]=b0; g_bb2_1[i]=b2;
        const float* s3=sb3+g*192;
        g_sb3[i]=s3[o]+s3[64+o]+s3[128+o];
        g_cst3[i]=tb3[i]+rb3[i]*rg3[i]*BNS+rbb3[i];
    }
    for (int i=gt;i<5*128;i+=NTH){
        int g=i/128, o=i%128;
        float b0=0.f,b1=0.f,b2=0.f;
        for (int c=0;c<128;c++){
            float sb = sb2[g*384+c]+sb2[g*384+128+c]+sb2[g*384+256+c];
            b0=fmaf(tw2[((g*128+o)*128+c)*3+0],sb,b0);
            b1=fmaf(tw2[((g*128+o)*128+c)*3+1],sb,b1);
            b2=fmaf(tw2[((g*128+o)*128+c)*3+2],sb,b2);
        }
        g_cst2[i]=tb2[i]+rb2[i]*rg2[i]*BNS+rbb2[i]+b0+b1+b2;
        g_bb0_2[i]=b0; g_bb2_2[i]=b2;
    }
    for (int i=gt;i<640;i+=NTH) g_zero[i]=0.f;
    if (gt==0){
        double fa[25][25];
        for (int i=0;i<25;i++) for (int j=0;j<25;j++) fa[i][j]=0.0;
        const int E[24][2]={{3,2},{2,20},{20,1},{1,0},{20,4},{4,5},{5,6},{6,22},
                            {6,7},{7,21},{20,8},{8,9},{9,10},{10,24},{10,11},{11,23},
                            {0,12},{12,13},{13,14},{14,15},{0,16},{16,17},{17,18},{18,19}};
        for (int k=0;k<24;k++){
            int i=E[k][0]-1, j=E[k][1]-1;
            fa[i][j]=1.0; fa[j][i]=1.0;
        }
        for (int i=0;i<25;i++) fa[i][i]+=1.0;
        for (int i=0;i<25;i++){
            double d=0; for (int j=0;j<25;j++) d+=fa[i][j];
            if (d==0.0) d=1.0;
            for (int j=0;j<25;j++) fa[i][j]/=d;
        }
        for (int g=0;g<5;g++){
            int n=c_gn[g];
            int js[6]; for (int u=0;u<n;u++) js[u]=c_s2j[c_gstart[g]+u];
            double sa[6][6];
            for (int u=0;u<n;u++) for (int v=0;v<n;v++) sa[u][v]=fa[js[u]][js[v]];
            for (int u=0;u<n;u++) sa[u][u]+=1.0;
            double dg[6];
            for (int u=0;u<n;u++){ double d=0; for (int v=0;v<n;v++) d+=sa[u][v]; dg[u]=d; }
            for (int node=1;node<n;node++)
                if (dg[node]==1.0){ sa[0][node]=1.0; sa[node][0]=1.0; }
            for (int u=0;u<6;u++) for (int v=0;v<6;v++){
                float val=0.f;
                if (u<n && v<n){
                    double d=0; for (int w=0;w<n;w++) d+=sa[u][w];
                    if (d==0.0) d=1.0;
                    val=(float)(sa[u][v]/d);
                }
                g_adj[g][u][v]=val;
            }
        }
    }
}

__global__ __launch_bounds__(256) void k_embed(const float* __restrict__ x,
                                               const float* __restrict__ ew,
                                               const float* __restrict__ eb)
{
    int idx = blockIdx.x*256 + threadIdx.x;
    int c   = idx & 63;
    int row = idx >> 6;
    int s   = row % 25;
    int bt  = row / 25;
    int j   = c_s2j[s];
    const float* xp = x + (bt*25 + j)*3;
    g_H[idx] = eb[c] + xp[0]*ew[c*3+0] + xp[1]*ew[c*3+1] + xp[2]*ew[c*3+2];
}

template<int CT>
__device__ __forceinline__ void gemm_kk4(unsigned long long (&acc)[6][4],
                                         const float4* aPtr, int aStride,
                                         const ulonglong2* wPtr)
{
    float4 a[6];
    #pragma unroll
    for (int i=0;i<6;++i) a[i] = aPtr[aStride*i];
    #pragma unroll
    for (int h=0;h<2;++h){
        ulonglong2 w0 = wPtr[h*4*CT + 0*CT];
        ulonglong2 w1 = wPtr[h*4*CT + 1*CT];
        ulonglong2 w2 = wPtr[h*4*CT + 2*CT];
        ulonglong2 w3 = wPtr[h*4*CT + 3*CT];
        #pragma unroll
        for (int i=0;i<6;++i){
            unsigned long long alo = bc2(h ? a[i].z : a[i].x);
            unsigned long long ahi = bc2(h ? a[i].w : a[i].y);
            ffma2(acc[i][0], alo, w0.x);
            ffma2(acc[i][1], alo, w1.x);
            ffma2(acc[i][2], alo, w2.x);
            ffma2(acc[i][3], alo, w3.x);
            ffma2(acc[i][0], ahi, w0.y);
            ffma2(acc[i][1], ahi, w1.y);
            ffma2(acc[i][2], ahi, w2.y);
            ffma2(acc[i][3], ahi, w3.y);
        }
    }
}

// Layer-3 GCN: graph conv + 128->64 GEMM, K-split staging, 192-row tiles, 256 thr.
__global__ __launch_bounds__(256) void k_gcn3(const float* __restrict__ Y,
                                              float* __restrict__ Z,
                                              const float4* __restrict__ Wi,
                                              const float* __restrict__ Bv)
{
    constexpr int CT = 8;
    extern __shared__ float sm[];
    float4* sA4 = (float4*)sm;                 // [192][17]
    float4* sW4 = sA4 + 192*17;                // [1024]
    const ulonglong2* sWl = (const ulonglong2*)sW4;
    __shared__ float sAdj[6][6];

    const int g   = blockIdx.y;
    const int n   = c_gn[g];
    const int gs0 = c_gstart[g];
    const int bt0 = blockIdx.x * 32;
    const int tid = threadIdx.x;
    if (tid < 36) sAdj[tid/6][tid%6] = g_adj[g][tid/6][tid%6];

    const int ty = tid / CT, tx = tid % CT;
    unsigned long long acc[6][4];
    #pragma unroll
    for (int jp=0;jp<4;++jp){
        int oa = tx + 16*jp;
        unsigned long long b2 = pk2(Bv[g*64+oa], Bv[g*64+oa+8]);
        #pragma unroll
        for (int i=0;i<6;++i) acc[i][jp]=b2;
    }
    const float4* Wg = Wi + (size_t)g*2048;

    for (int ph=0; ph<2; ++ph){
        __syncthreads();
        for (int p=tid; p<192*16; p+=256){
            int c4l = p % 16, r = p / 16, u = r % 6, t = r / 6;
            int c4 = ph*16 + c4l;
            float4 v = make_float4(0.f,0.f,0.f,0.f);
            if (u < n){
                const float4* yp = (const float4*)(Y + ((size_t)(bt0+t)*25 + gs0)*128) + c4;
                #pragma unroll
                for (int vv=0; vv<6; ++vv)
                    if (vv < n){
                        float av = sAdj[u][vv];
                        float4 yv = yp[(size_t)vv*32];
                        v.x += av*yv.x; v.y += av*yv.y; v.z += av*yv.z; v.w += av*yv.w;
                    }
            }
            sA4[r*17 + c4l] = v;
        }
        for (int p=tid; p<1024; p+=256) sW4[p] = Wg[ph*1024 + p];
        __syncthreads();
        #pragma unroll 8
        for (int kk4l=0;kk4l<16;++kk4l)
            gemm_kk4<CT>(acc, sA4 + ty*17 + kk4l, 32*17, sWl + 2*kk4l*4*CT + tx);
    }

    #pragma unroll
    for (int i=0;i<6;++i){
        int r = ty+32*i, t = r/6, u = r%6;
        if (u < n){
            float* zp = Z + ((size_t)(bt0+t)*25 + gs0+u)*64;
            #pragma unroll
            for (int jp=0;jp<4;++jp){
                float lo,hi; unpk(acc[i][jp], lo, hi);
                int oa = tx + 16*jp;
                zp[oa] = lo; zp[oa+8] = hi;
            }
        }
    }
}

// tconv: TBL=16, per-kt W staging, optional fused graph conv on staging. CIN=64.
template<int CIN,int COUT,int CRES,int MODE,int GCONV>
__global__ __launch_bounds__((COUT/8)*16)
void k_tconv(const float* __restrict__ Zin, const float* __restrict__ Yres,
             float* __restrict__ Yout,
             const float4* __restrict__ TWi, const float4* __restrict__ RWi,
             const float* __restrict__ CST, const float* __restrict__ BB0,
             const float* __restrict__ BB2,
             const float* __restrict__ GS, const float* __restrict__ BB)
{
    constexpr int CT  = COUT/8;
    constexpr int TH  = CT*16;
    constexpr int C4  = CIN/4;   // 16
    constexpr int C2  = CIN/2;
    constexpr int PRZ = C4+1;    // 17
    constexpr int TBL = 16;
    constexpr int WKT = C2*4*CT;            // per-kt W float4s
    constexpr int SBUF4 = (TBL+2)*6*PRZ;    // 1836
    extern __shared__ float sm[];
    float4* sB4 = (float4*)sm;
    float4* sW4 = sB4 + SBUF4;
    const ulonglong2* sWl = (const ulonglong2*)sW4;
    __shared__ float sAdj[6][6];

    const int g   = blockIdx.y;
    const int n   = c_gn[g];
    const int gs0 = c_gstart[g];
    const int bt0 = blockIdx.x * TBL;
    const int t0  = bt0 & (NT-1);
    const int tid = threadIdx.x, ty = tid/CT, tx = tid%CT;

    if (GCONV){
        if (tid < 36) sAdj[tid/6][tid%6] = g_adj[g][tid/6][tid%6];
        __syncthreads();
    }

    for (int p=tid; p<(TBL+2)*6*C4; p+=TH){
        int c4 = p % C4, r = p / C4, u = r % 6, hb = r / 6;
        int t = t0 + hb - 1;
        float4 v = make_float4(0.f,0.f,0.f,0.f);
        if (t >= 0 && t < NT){
            if (GCONV){
                const float4* yp = (const float4*)(Zin + ((size_t)(bt0+hb-1)*25 + gs0)*CIN) + c4;
                #pragma unroll
                for (int vv=0; vv<6; ++vv)
                    if (vv < n){
                        float av = sAdj[u][vv];
                        float4 yv = yp[(size_t)vv*C4];
                        v.x += av*yv.x; v.y += av*yv.y; v.z += av*yv.z; v.w += av*yv.w;
                    }
            } else if (u < n){
                v = ((const float4*)(Zin + ((size_t)(bt0+hb-1)*25 + gs0+u)*CIN))[c4];
            }
        }
        sB4[r*PRZ + c4] = v;
    }

    unsigned long long acc[6][4];
    unsigned long long z2 = pk2(0.f, 0.f);
    #pragma unroll
    for (int i=0;i<6;++i)
        #pragma unroll
        for (int jp=0;jp<4;++jp) acc[i][jp]=z2;

    const float4* TWg = TWi + (size_t)g*3*WKT;
    for (int kt=0;kt<3;++kt){
        __syncthreads();
        for (int p=tid; p<WKT; p+=TH) sW4[p] = TWg[kt*WKT + p];
        __syncthreads();
        #pragma unroll 8
        for (int kk4=0;kk4<C4;++kk4)
            gemm_kk4<CT>(acc, sB4 + (ty+6*kt)*PRZ + kk4, 16*PRZ,
                         sWl + 2*kk4*4*CT + tx);
    }

    if (MODE==1){
        constexpr int RPASS = CRES/64;
        constexpr int RWP   = 32*4*CT;
        const float4* RWg = RWi + (size_t)g*2048;
        for (int ph=0; ph<RPASS; ++ph){
            __syncthreads();
            for (int p=tid; p<96*16; p+=TH){
                int c4l = p % 16, r = p / 16, u = r % 6, t = r / 6;
                float4 v = make_float4(0.f,0.f,0.f,0.f);
                if (u < n)
                    v = ((const float4*)(Yres + ((size_t)(bt0+t)*25 + gs0+u)*CRES))[ph*16 + c4l];
                sB4[r*17 + c4l] = v;
            }
            for (int p=tid; p<RWP; p+=TH) sW4[p] = RWg[ph*RWP + p];
            __syncthreads();
            #pragma unroll 8
            for (int kk4l=0;kk4l<16;++kk4l)
                gemm_kk4<CT>(acc, sB4 + ty*17 + kk4l, 16*17, sWl + 2*kk4l*4*CT + tx);
        }
    }

    float cst[8], gsv[8], bbv[8];
    #pragma unroll
    for (int jp=0;jp<4;++jp){
        int oa = tx + CT*2*jp;
        cst[2*jp]   = CST[g*COUT+oa];       cst[2*jp+1] = CST[g*COUT+oa+CT];
        gsv[2*jp]   = GS [g*COUT+oa]*BNS;   gsv[2*jp+1] = GS [g*COUT+oa+CT]*BNS;
        bbv[2*jp]   = BB [g*COUT+oa];       bbv[2*jp+1] = BB [g*COUT+oa+CT];
    }
    #pragma unroll
    for (int i=0;i<6;++i){
        int r = ty+16*i, t = r/6, u = r%6;
        if (u < n){
            size_t base = ((size_t)(bt0+t)*25 + gs0+u)*COUT;
            int tg = t0 + t;
            bool e0 = (tg==0), e2 = (tg==NT-1);
            #pragma unroll
            for (int jp=0;jp<4;++jp){
                float lo,hi; unpk(acc[i][jp], lo, hi);
                int oa = tx + CT*2*jp;
                float pa = lo + cst[2*jp];
                float pb = hi + cst[2*jp+1];
                if (e0){ pa -= BB0[g*COUT+oa]; pb -= BB0[g*COUT+oa+CT]; }
                if (e2){ pa -= BB2[g*COUT+oa]; pb -= BB2[g*COUT+oa+CT]; }
                if (MODE==0){ pa += Yres[base+oa]; pb += Yres[base+oa+CT]; }
                Yout[base+oa]    = fmaxf(pa*gsv[2*jp]   + bbv[2*jp],   0.f);
                Yout[base+oa+CT] = fmaxf(pb*gsv[2*jp+1] + bbv[2*jp+1], 0.f);
            }
        }
    }
}

// fused feature-mean + VQ
__global__ __launch_bounds__(256) void k_featvq(const float* __restrict__ cb,
                                                float* __restrict__ out)
{
    int g = blockIdx.x, b = blockIdx.y;
    int tid = threadIdx.x;
    int o = tid & 63, part = tid >> 6;
    int n = c_gn[g], gs0 = c_gstart[g];
    float s = 0.f;
    int total = NT*n;
    for (int q=part; q<total; q+=4){
        int t = q / n, u = q % n;
        s += g_Y3[((size_t)(b*NT+t)*25 + gs0+u)*64 + o];
    }
    __shared__ float red[256];
    __shared__ float f[64];
    red[tid]=s; __syncthreads();
    if (part==0)
        f[o] = (red[o]+red[64+o]+red[128+o]+red[192+o]) / (float)(NT*n);
    __syncthreads();

    __shared__ float ds[128];
    __shared__ int   sidx;
    if (tid < 128){
        const float* ck = cb + (g*128 + tid)*64;
        float dot=0.f, scb=0.f;
        for (int oo=0;oo<64;++oo){ dot += f[oo]*ck[oo]; scb += ck[oo]*ck[oo]; }
        ds[tid] = scb - 2.f*dot;
    }
    __syncthreads();
    if (tid==0){
        float best = ds[0]; int bi = 0;
        for (int kk=1;kk<128;++kk) if (ds[kk] < best){ best = ds[kk]; bi = kk; }
        sidx = bi;
    }
    __syncthreads();
    int idx = sidx;
    __shared__ float dsq[64];
    if (tid < 64){
        float q = cb[(g*128 + idx)*64 + tid];
        out[(g*64+b)*64 + tid] = q;
        float dd = q - f[tid];
        dsq[tid] = dd*dd;
    }
    __syncthreads();
    if (tid==0){
        float ss=0.f;
        for (int oo=0;oo<64;++oo) ss += dsq[oo];
        g_loss[g*64+b] = 1.25f * ss / 4096.f;
        out[5*64*64 + 1 + g*64 + b] = (float)idx;
    }
}

__global__ void k_lred(float* out){
    __shared__ float s[320];
    int t = threadIdx.x;
    if (t < 320) s[t] = g_loss[t];
    __syncthreads();
    if (t==0){
        float a=0.f;
        for (int i=0;i<320;i++) a += s[i];
        out[5*64*64] = a;
    }
}

extern "C" void kernel_launch(void* const* d_in, const int* in_sizes, int n_in,
                              void* d_out, int out_size)
{
    const float* x        = (const float*)d_in[0];
    const float* embed_w  = (const float*)d_in[1];
    const float* embed_b  = (const float*)d_in[2];
    const float* sgcn_w1  = (const float*)d_in[3];
    const float* sgcn_b1  = (const float*)d_in[4];
    const float* tconv_w1 = (const float*)d_in[5];
    const float* tconv_b1 = (const float*)d_in[6];
    const float* bn_g1    = (const float*)d_in[7];
    const float* bn_b1    = (const float*)d_in[8];
    const float* res_w2   = (const float*)d_in[9];
    const float* res_b2   = (const float*)d_in[10];
    const float* resbn_g2 = (const float*)d_in[11];
    const float* resbn_b2 = (const float*)d_in[12];
    const float* sgcn_w2  = (const float*)d_in[13];
    const float* sgcn_b2  = (const float*)d_in[14];
    const float* tconv_w2 = (const float*)d_in[15];
    const float* tconv_b2 = (const float*)d_in[16];
    const float* bn_g2    = (const float*)d_in[17];
    const float* bn_b2    = (const float*)d_in[18];
    const float* res_w3   = (const float*)d_in[19];
    const float* res_b3   = (const float*)d_in[20];
    const float* resbn_g3 = (const float*)d_in[21];
    const float* resbn_b3 = (const float*)d_in[22];
    const float* sgcn_w3  = (const float*)d_in[23];
    const float* sgcn_b3  = (const float*)d_in[24];
    const float* tconv_w3 = (const float*)d_in[25];
    const float* tconv_b3 = (const float*)d_in[26];
    const float* bn_g3    = (const float*)d_in[27];
    const float* bn_b3    = (const float*)d_in[28];
    const float* codebooks= (const float*)d_in[29];
    float* out = (float*)d_out;

    void *vp;
    #define SYM(name, s, T) cudaGetSymbolAddress(&vp, s); T* name = (T*)vp;
    SYM(pH,  g_H,  float)  SYM(pZ, g_Z, float)  SYM(pY1, g_Y1, float)
    SYM(pY2, g_Y2, float)  SYM(pY3, g_Y3, float)
    SYM(pSB3,g_sb3,float)
    SYM(pC1, g_cst1,float) SYM(pB01,g_bb0_1,float) SYM(pB21,g_bb2_1,float)
    SYM(pC2, g_cst2,float) SYM(pB02,g_bb0_2,float) SYM(pB22,g_bb2_2,float)
    SYM(pC3, g_cst3,float) SYM(pZERO,g_zero,float)
    SYM(pSW3,g_sw3i,float4)
    SYM(pRW2,g_rw2i,float4) SYM(pRW3,g_rw3i,float4)
    SYM(pTW1,g_tw1i,float4) SYM(pTW2,g_tw2i,float4) SYM(pTW3,g_tw3i,float4)
    #undef SYM

    dim3 grid16(BT/16, 5);   // 1024 x 5
    dim3 grid32(BT/32, 5);   // 512 x 5

    size_t sm_t1 = (1836 + 1024)*16;   // 45.8 KB
    size_t sm_t2 = (1836 + 2048)*16;   // 62.1 KB
    size_t sm_t3 = sm_t1;
    size_t sm_g3 = (192*17 + 1024)*16; // 68.6 KB

    cudaFuncSetAttribute(k_tconv<64,64,64,0,1>,   cudaFuncAttributeMaxDynamicSharedMemorySize, (int)sm_t1);
    cudaFuncSetAttribute(k_tconv<64,128,64,1,1>,  cudaFuncAttributeMaxDynamicSharedMemorySize, (int)sm_t2);
    cudaFuncSetAttribute(k_gcn3,                  cudaFuncAttributeMaxDynamicSharedMemorySize, (int)sm_g3);
    cudaFuncSetAttribute(k_tconv<64,64,128,1,0>,  cudaFuncAttributeMaxDynamicSharedMemorySize, (int)sm_t3);

    k_prep<<<64,256>>>(sgcn_w1, sgcn_b1, tconv_w1, tconv_b1,
                       res_w2, res_b2, resbn_g2, resbn_b2, sgcn_w2, sgcn_b2, tconv_w2, tconv_b2,
                       res_w3, res_b3, resbn_g3, resbn_b3, sgcn_w3, sgcn_b3, tconv_w3, tconv_b3);

    k_embed<<<BT*25*64/256, 256>>>(x, embed_w, embed_b);

    k_tconv<64,64,64,0,1><<<grid16,128,sm_t1>>>(pH, pH, pY1, pTW1, pRW2,
                                                pC1, pB01, pB21, bn_g1, bn_b1);
    k_tconv<64,128,64,1,1><<<grid16,256,sm_t2>>>(pY1, pY1, pY2, pTW2, pRW2,
                                                 pC2, pB02, pB22, bn_g2, bn_b2);
    k_gcn3<<<grid32,256,sm_g3>>>(pY2, pZ, pSW3, pSB3);
    k_tconv<64,64,128,1,0><<<grid16,128,sm_t3>>>(pZ, pY2, pY3, pTW3, pRW3,
                                                 pC3, pZERO, pZERO, bn_g3, bn_b3);

    k_featvq<<<dim3(5,64),256>>>(codebooks, out);
    k_lred<<<1,512>>>(out);
}